// round 6
// baseline (speedup 1.0000x reference)
#include <cuda_runtime.h>
#include <cstdint>

#define B_  32
#define T_  512
#define H_  512
#define NB  256
#define MAXL 2048

// packed activation geometry: [b][chunk 16][514 rows][36 cols]
#define APB    (514 * 36)
#define A_BSTR (16 * APB)
#define PSTR   (32 * A_BSTR)
// packed weight geometry: [pred 3][ntile 2][stage 48][32][264]
#define B_SLOT_F (32 * 264)
#define WP_F (3 * 2 * 48 * B_SLOT_F)

// ---------------- scratch ----------------
__device__ __align__(256) float g_xp [32 * A_BSTR];
__device__ __align__(256) float g_x2p[32 * A_BSTR];
__device__ __align__(256) float g_h1p[3 * PSTR];
__device__ __align__(256) float g_w1p[WP_F];
__device__ __align__(256) float g_w2p[WP_F];
__device__ __align__(256) float g_h2 [3 * B_ * T_ * H_];
__device__ float g_x2 [B_ * T_ * H_];
__device__ int   g_cum[B_ * T_];
__device__ int   g_ml [B_];

__device__ __forceinline__ uint32_t smem_u32(const void* p) {
    uint32_t a;
    asm("{ .reg .u64 t; cvta.to.shared.u64 t, %1; cvt.u32.u64 %0, t; }" : "=r"(a) : "l"(p));
    return a;
}
__device__ __forceinline__ float rna_tf32(float v) {
    uint32_t u;
    asm("cvt.rna.tf32.f32 %0, %1;" : "=r"(u) : "f"(v));
    return __uint_as_float(u);
}
__device__ __forceinline__ float4 rna4(float4 v) {
    return make_float4(rna_tf32(v.x), rna_tf32(v.y), rna_tf32(v.z), rna_tf32(v.w));
}

#define MBAR_INIT(a, n) \
    asm volatile("mbarrier.init.shared.b64 [%0], %1;" :: "r"(a), "r"(n) : "memory")
#define MBAR_EXPECT(a, bytes) \
    asm volatile("mbarrier.arrive.expect_tx.shared.b64 _, [%0], %1;" :: "r"(a), "r"(bytes) : "memory")
#define MBAR_WAIT(a, par) do {                                                   \
    uint32_t _m = (a); uint32_t _p = (par); uint32_t _d;                         \
    asm volatile("{ .reg .pred p;"                                               \
        " mbarrier.try_wait.parity.acquire.cta.shared::cta.b64 p, [%1], %2;"     \
        " selp.b32 %0, 1, 0, p; }" : "=r"(_d) : "r"(_m), "r"(_p) : "memory");    \
    if (!_d) {                                                                   \
        asm volatile("{ .reg .pred P1;"                                          \
            " WL_%=:"                                                            \
            " mbarrier.try_wait.parity.acquire.cta.shared::cta.b64 P1, [%0], %1, 0x989680;" \
            " @P1 bra.uni WD_%=;"                                                \
            " bra.uni WL_%=;"                                                    \
            " WD_%=: }" :: "r"(_m), "r"(_p) : "memory");                         \
    } } while (0)

__device__ __forceinline__ void bulk_ld(uint32_t dst, const void* src,
                                        uint32_t bytes, uint32_t mbar) {
    asm volatile(
        "cp.async.bulk.shared::cluster.global.mbarrier::complete_tx::bytes "
        "[%0], [%1], %2, [%3];"
        :: "r"(dst), "l"(src), "r"(bytes), "r"(mbar) : "memory");
}

// ---------------------------------------------------------------------------
// conv1d(K=3,pad=1) implicit GEMM, mma.sync tf32, bulk-copy pipeline.
// CTA tile M=128 x N=256. 8 warps in 2(M) x 4(N); warp tile 64x64.
// Grid (4 Mtile, 2 Ntile, 96 = pred*32+b). Block 256.
// smem: 64B mbar | A 2x18720 | B 3x33792 = 138880 B (1 CTA/SM)
// ---------------------------------------------------------------------------
#define A_BYTES 18720            // 130*36*4
#define B_BYTES 33792            // 32*264*4
#define SA_OFF  64
#define SB_OFF  (64 + 2 * A_BYTES)
#define CONV_SMEM (SB_OFF + 3 * B_BYTES)

extern __shared__ __align__(128) char csm[];

__global__ void __launch_bounds__(256, 1) conv_bulk_kernel(
    const float* __restrict__ in0, const float* __restrict__ in1,
    const float* __restrict__ in2, const float* __restrict__ wpk,
    const float* __restrict__ biasAll,
    float* __restrict__ outBase, size_t outPredStride, int packedOut)
{
    const uint32_t sb = smem_u32(csm);
    float* smf = (float*)csm;
    const int tid  = threadIdx.x;
    const int lane = tid & 31, wid = tid >> 5;
    const int wmm = wid & 1, wnn = wid >> 1;     // 2 x 4 warp grid
    const int t0 = blockIdx.x * 128;
    const int n0 = blockIdx.y * 256;
    const int pred = blockIdx.z >> 5;
    const int b    = blockIdx.z & 31;

    const float* inP = (pred == 0) ? in0 : (pred == 1) ? in1 : in2;
    const float* aSrc = inP + (size_t)b * A_BSTR + (size_t)t0 * 36;
    const float* wB = wpk + (size_t)(pred * 2 + blockIdx.y) * 48 * B_SLOT_F;
    const float* biasP = biasAll + pred * 512;

    if (tid == 0) {
#pragma unroll
        for (int i = 0; i < 5; i++) MBAR_INIT(sb + i * 8, 1);
    }
    __syncthreads();

#define ISSUE_A(c) do {                                                        \
    uint32_t mb = sb + ((c) & 1) * 8;                                          \
    MBAR_EXPECT(mb, A_BYTES);                                                  \
    bulk_ld(sb + SA_OFF + ((c) & 1) * A_BYTES, aSrc + (size_t)(c) * APB,       \
            A_BYTES, mb); } while (0)
#define ISSUE_B(s) do {                                                        \
    uint32_t mb = sb + 16 + ((s) % 3) * 8;                                     \
    MBAR_EXPECT(mb, B_BYTES);                                                  \
    bulk_ld(sb + SB_OFF + ((s) % 3) * B_BYTES, wB + (size_t)(s) * B_SLOT_F,    \
            B_BYTES, mb); } while (0)

    if (tid == 0) { ISSUE_A(0); ISSUE_B(0); ISSUE_B(1); }

    float acc[4][8][4];
#pragma unroll
    for (int mi = 0; mi < 4; mi++)
#pragma unroll
        for (int ni = 0; ni < 8; ni++)
#pragma unroll
            for (int q = 0; q < 4; q++) acc[mi][ni][q] = 0.f;

    int c = 0, tap = 0;
    for (int s = 0; s < 48; ++s) {
        if (tid == 0) {
            if (tap == 0 && c + 1 < 16) ISSUE_A(c + 1);
            if (s + 2 < 48) ISSUE_B(s + 2);
        }
        MBAR_WAIT(sb + 16 + (s % 3) * 8, (s / 3) & 1);
        if (tap == 0) MBAR_WAIT(sb + (c & 1) * 8, (c >> 1) & 1);

        const float* A  = smf + (SA_OFF >> 2) + (c & 1) * (A_BYTES >> 2)
                        + (wmm * 64 + tap + (lane >> 2)) * 36;
        const float* Bp = smf + (SB_OFF >> 2) + (s % 3) * (B_BYTES >> 2)
                        + (lane & 3) * 264 + wnn * 64 + (lane >> 2);
#pragma unroll
        for (int kk = 0; kk < 4; kk++) {
            uint32_t a[4][4], bb[8][2];
            const float* Ak = A + kk * 8 + (lane & 3);
#pragma unroll
            for (int mi = 0; mi < 4; mi++) {
                const float* Am = Ak + mi * 16 * 36;
                a[mi][0] = __float_as_uint(Am[0]);
                a[mi][1] = __float_as_uint(Am[8 * 36]);
                a[mi][2] = __float_as_uint(Am[4]);
                a[mi][3] = __float_as_uint(Am[8 * 36 + 4]);
            }
            const float* Bk = Bp + kk * 8 * 264;
#pragma unroll
            for (int ni = 0; ni < 8; ni++) {
                bb[ni][0] = __float_as_uint(Bk[ni * 8]);
                bb[ni][1] = __float_as_uint(Bk[4 * 264 + ni * 8]);
            }
#pragma unroll
            for (int mi = 0; mi < 4; mi++)
#pragma unroll
                for (int ni = 0; ni < 8; ni++)
                    asm volatile(
                        "mma.sync.aligned.m16n8k8.row.col.f32.tf32.tf32.f32 "
                        "{%0,%1,%2,%3}, {%4,%5,%6,%7}, {%8,%9}, {%0,%1,%2,%3};"
                        : "+f"(acc[mi][ni][0]), "+f"(acc[mi][ni][1]),
                          "+f"(acc[mi][ni][2]), "+f"(acc[mi][ni][3])
                        : "r"(a[mi][0]), "r"(a[mi][1]), "r"(a[mi][2]), "r"(a[mi][3]),
                          "r"(bb[ni][0]), "r"(bb[ni][1]));
        }
        __syncthreads();
        if (++tap == 3) { tap = 0; ++c; }
    }

    // epilogue: bias + ReLU
    const int r0 = wmm * 64 + (lane >> 2);
    const int c0 = wnn * 64 + (lane & 3) * 2;
    if (packedOut) {
        float* ob = outBase + (size_t)pred * outPredStride + (size_t)b * A_BSTR;
#pragma unroll
        for (int ni = 0; ni < 8; ni++) {
            int col = n0 + c0 + ni * 8;
            int ch = col >> 5, k = col & 31;
            float b0 = __ldg(&biasP[col]), b1 = __ldg(&biasP[col + 1]);
            float* cb = ob + (size_t)ch * APB + k;
#pragma unroll
            for (int mi = 0; mi < 4; mi++) {
                int row = t0 + r0 + mi * 16;
                float v0 = fmaxf(acc[mi][ni][0] + b0, 0.f);
                float v1 = fmaxf(acc[mi][ni][1] + b1, 0.f);
                float v2 = fmaxf(acc[mi][ni][2] + b0, 0.f);
                float v3 = fmaxf(acc[mi][ni][3] + b1, 0.f);
                *(float2*)&cb[(size_t)(row + 1) * 36] = make_float2(v0, v1);
                *(float2*)&cb[(size_t)(row + 9) * 36] = make_float2(v2, v3);
            }
        }
    } else {
        float* ob = outBase + (size_t)pred * outPredStride + (size_t)b * (512 * 512);
#pragma unroll
        for (int ni = 0; ni < 8; ni++) {
            int col = n0 + c0 + ni * 8;
            float b0 = __ldg(&biasP[col]), b1 = __ldg(&biasP[col + 1]);
#pragma unroll
            for (int mi = 0; mi < 4; mi++) {
                int row = t0 + r0 + mi * 16;
                float v0 = fmaxf(acc[mi][ni][0] + b0, 0.f);
                float v1 = fmaxf(acc[mi][ni][1] + b1, 0.f);
                float v2 = fmaxf(acc[mi][ni][2] + b0, 0.f);
                float v3 = fmaxf(acc[mi][ni][3] + b1, 0.f);
                *(float2*)&ob[(size_t)row * 512 + col]       = make_float2(v0, v1);
                *(float2*)&ob[(size_t)(row + 8) * 512 + col] = make_float2(v2, v3);
            }
        }
    }
}

// pack weights: w[pred][tap][cin][cout] -> wp[pred][nt 2][st 48][k 32][264], tf32
__global__ void __launch_bounds__(256) pack_w_kernel(
    const float* __restrict__ w, float* __restrict__ wp)
{
    int g = blockIdx.x * 256 + threadIdx.x;          // 589824 threads
    int n4 = g & 63;
    int k  = (g >> 6) & 31;
    int x  = g >> 11;                                 // 0..287
    int st = x % 48;
    int nt = (x / 48) & 1;
    int pr = x / 96;
    int tap = st % 3, ch = st / 3;
    float4 v = *(const float4*)&w[(size_t)((pr * 3 + tap) * 512 + ch * 32 + k) * 512
                                  + nt * 256 + n4 * 4];
    *(float4*)&wp[(size_t)(((pr * 2 + nt) * 48 + st) * 32 + k) * 264 + n4 * 4] = rna4(v);
}

// pack tokens: src[b][t][512] -> dst[b][chunk][514][36] (halo rows zero), tf32
__global__ void __launch_bounds__(256) pack_tok_kernel(
    const float* __restrict__ src, float* __restrict__ dst)
{
    int g = blockIdx.x * 256 + threadIdx.x;
    int k4 = g & 7;
    int r  = (g >> 3) % 514;
    int x  = (g >> 3) / 514;
    int ch = x & 15, b = x >> 4;
    float4 o = make_float4(0.f, 0.f, 0.f, 0.f);
    if (r != 0 && r != 513) {
        float4 v = *(const float4*)&src[(size_t)b * 262144 + (size_t)(r - 1) * 512
                                        + ch * 32 + k4 * 4];
        o = rna4(v);
    }
    *(float4*)&dst[((size_t)(b * 16 + ch) * 514 + r) * 36 + k4 * 4] = o;
}

__global__ void __launch_bounds__(256) zero_halo_kernel(float* __restrict__ hp)
{
    int g = blockIdx.x * 256 + threadIdx.x;
    if (g >= 3 * 32 * 16 * 2 * 9) return;
    int k4 = g % 9;
    int h  = (g / 9) & 1;
    int ch = (g / 18) & 15;
    int b  = (g / 288) & 31;
    int pr = g / 9216;
    *(float4*)&hp[(size_t)pr * PSTR + (size_t)(b * 16 + ch) * APB
                  + (size_t)(h ? 513 : 0) * 36 + k4 * 4] = make_float4(0, 0, 0, 0);
}

// LayerNorm on packed layout, in place, tf32-rounds output. 3 preds batched.
__global__ void __launch_bounds__(256) ln_packed_kernel(
    float* __restrict__ hp, const float* __restrict__ gAll,
    const float* __restrict__ btAll)
{
    int bid = blockIdx.x;
    int pred = bid >> 11, rem = bid & 2047;
    int b = rem >> 6, tg = rem & 63;
    int wid = threadIdx.x >> 5, lane = threadIdx.x & 31;
    int t = tg * 8 + wid;
    float* base = hp + (size_t)pred * PSTR + (size_t)b * A_BSTR
                + (size_t)(t + 1) * 36 + lane;
    const float* g  = gAll + pred * 512;
    const float* bt = btAll + pred * 512;
    float v[16], s = 0.f, s2 = 0.f;
#pragma unroll
    for (int j = 0; j < 16; j++) {
        v[j] = base[(size_t)j * APB];
        s += v[j]; s2 += v[j] * v[j];
    }
#pragma unroll
    for (int o = 16; o; o >>= 1) {
        s  += __shfl_xor_sync(0xffffffffu, s,  o);
        s2 += __shfl_xor_sync(0xffffffffu, s2, o);
    }
    float mean = s * (1.f / 512.f);
    float var  = s2 * (1.f / 512.f) - mean * mean;
    float rs   = rsqrtf(var + 1e-5f);
#pragma unroll
    for (int j = 0; j < 16; j++) {
        int f = j * 32 + lane;
        base[(size_t)j * APB] = rna_tf32((v[j] - mean) * rs * g[f] + bt[f]);
    }
}

// LN + linear head on linear h2; 3 preds batched.
__global__ void __launch_bounds__(256) ln_head_kernel(
    const float* __restrict__ h2, const float* __restrict__ gAll,
    const float* __restrict__ btAll, const float* __restrict__ lwAll,
    const float* __restrict__ lb, float* __restrict__ outPred)
{
    int bid = blockIdx.x;
    int pred = bid >> 11;
    int token = (bid & 2047) * 8 + (threadIdx.x >> 5);
    int lane  = threadIdx.x & 31;
    const float* hr = h2 + (size_t)pred * (B_ * T_ * H_) + (size_t)token * 512;
    const float* g  = gAll + pred * 512;
    const float* bt = btAll + pred * 512;
    const float* lw = lwAll + pred * 512;
    float v[16], s = 0.f, s2 = 0.f;
#pragma unroll
    for (int k = 0; k < 16; k++) {
        v[k] = hr[lane + 32 * k];
        s += v[k]; s2 += v[k] * v[k];
    }
#pragma unroll
    for (int o = 16; o; o >>= 1) {
        s  += __shfl_xor_sync(0xffffffffu, s,  o);
        s2 += __shfl_xor_sync(0xffffffffu, s2, o);
    }
    float mean = s * (1.f / 512.f);
    float var  = s2 * (1.f / 512.f) - mean * mean;
    float rs   = rsqrtf(var + 1e-5f);
    float dot = 0.f;
#pragma unroll
    for (int k = 0; k < 16; k++) {
        int f = lane + 32 * k;
        dot += ((v[k] - mean) * rs * g[f] + bt[f]) * lw[f];
    }
#pragma unroll
    for (int o = 16; o; o >>= 1) dot += __shfl_xor_sync(0xffffffffu, dot, o);
    if (lane == 0) outPred[(size_t)pred * (B_ * T_) + token] = dot + lb[pred];
}

__global__ void __launch_bounds__(128) embed_add_kernel(
    const float* __restrict__ xin, const float* __restrict__ target,
    const float* __restrict__ bins, const float* __restrict__ table,
    float* __restrict__ xout)
{
    int token = blockIdx.x;
    float tv = target[token];
    int lo = 0, hi = NB - 1;
    while (lo < hi) {
        int mid = (lo + hi) >> 1;
        if (bins[mid] < tv) lo = mid + 1; else hi = mid;
    }
    const float4* xi = (const float4*)(xin + (size_t)token * H_);
    const float4* tb = (const float4*)(table + (size_t)lo * H_);
    int i = threadIdx.x;
    float4 a = xi[i], c = tb[i];
    ((float4*)(xout + (size_t)token * H_))[i] =
        make_float4(a.x + c.x, a.y + c.y, a.z + c.z, a.w + c.w);
}

__global__ void __launch_bounds__(512) cumsum_kernel(
    const int* __restrict__ dur, int* __restrict__ cum,
    int* __restrict__ mellen, float* __restrict__ out_mellen)
{
    __shared__ int s[512];
    int b = blockIdx.x, t = threadIdx.x;
    s[t] = dur[b * T_ + t];
    __syncthreads();
    for (int off = 1; off < 512; off <<= 1) {
        int v = (t >= off) ? s[t - off] : 0;
        __syncthreads();
        s[t] += v;
        __syncthreads();
    }
    cum[b * T_ + t] = s[t];
    if (t == 511) {
        int ml = s[511] < MAXL ? s[511] : MAXL;
        mellen[b] = ml;
        out_mellen[b] = (float)ml;
    }
}

__global__ void __launch_bounds__(128) expand_kernel(
    const float* __restrict__ x3, const int* __restrict__ cum,
    const int* __restrict__ mellen, float* __restrict__ outx,
    float* __restrict__ outmask)
{
    int frame = blockIdx.x, b = blockIdx.y;
    int ml = mellen[b];
    float* orow = outx + ((size_t)b * MAXL + frame) * H_;
    bool masked = frame >= ml;
    if (threadIdx.x == 0) outmask[b * MAXL + frame] = masked ? 1.0f : 0.0f;
    if (masked) {
        ((float4*)orow)[threadIdx.x] = make_float4(0, 0, 0, 0);
        return;
    }
    const int* cb = cum + b * T_;
    int lo = 0, hi = T_;
    while (lo < hi) {
        int mid = (lo + hi) >> 1;
        if (cb[mid] <= frame) lo = mid + 1; else hi = mid;
    }
    if (lo > T_ - 1) lo = T_ - 1;
    ((float4*)orow)[threadIdx.x] =
        ((const float4*)(x3 + ((size_t)b * T_ + lo) * H_))[threadIdx.x];
}

extern "C" void kernel_launch(void* const* d_in, const int* in_sizes, int n_in,
                              void* d_out, int out_size)
{
    const float* x        = (const float*)d_in[0];
    const int*   duration = (const int*)  d_in[2];
    const float* pitch_t  = (const float*)d_in[3];
    const float* energy_t = (const float*)d_in[4];
    const float* c1w = (const float*)d_in[5];
    const float* c1b = (const float*)d_in[6];
    const float* g1  = (const float*)d_in[7];
    const float* b1  = (const float*)d_in[8];
    const float* c2w = (const float*)d_in[9];
    const float* c2b = (const float*)d_in[10];
    const float* g2  = (const float*)d_in[11];
    const float* b2  = (const float*)d_in[12];
    const float* lw  = (const float*)d_in[13];
    const float* lb  = (const float*)d_in[14];
    const float* pbins = (const float*)d_in[15];
    const float* ebins = (const float*)d_in[16];
    const float* ptab  = (const float*)d_in[17];
    const float* etab  = (const float*)d_in[18];

    float* out = (float*)d_out;
    const size_t OFF_X      = 0;
    const size_t OFF_LOGDUR = (size_t)B_ * MAXL * H_;
    const size_t OFF_MELLEN = OFF_LOGDUR + 3 * (size_t)B_ * T_;
    const size_t OFF_MASK   = OFF_MELLEN + B_;

    float *p_xp, *p_x2p, *p_h1p, *p_w1p, *p_w2p, *p_h2, *p_x2;
    int *p_cum, *p_ml;
    cudaGetSymbolAddress((void**)&p_xp,  g_xp);
    cudaGetSymbolAddress((void**)&p_x2p, g_x2p);
    cudaGetSymbolAddress((void**)&p_h1p, g_h1p);
    cudaGetSymbolAddress((void**)&p_w1p, g_w1p);
    cudaGetSymbolAddress((void**)&p_w2p, g_w2p);
    cudaGetSymbolAddress((void**)&p_h2,  g_h2);
    cudaGetSymbolAddress((void**)&p_x2,  g_x2);
    cudaGetSymbolAddress((void**)&p_cum, g_cum);
    cudaGetSymbolAddress((void**)&p_ml,  g_ml);

    cudaFuncSetAttribute(conv_bulk_kernel,
                         cudaFuncAttributeMaxDynamicSharedMemorySize, CONV_SMEM);

    // ---- prep ----
    pack_w_kernel<<<2304, 256>>>(c1w, p_w1p);
    pack_w_kernel<<<2304, 256>>>(c2w, p_w2p);
    pack_tok_kernel<<<8224, 256>>>(x, p_xp);
    embed_add_kernel<<<B_ * T_, 128>>>(x, pitch_t, pbins, ptab, p_x2);
    pack_tok_kernel<<<8224, 256>>>(p_x2, p_x2p);
    zero_halo_kernel<<<108, 256>>>(p_h1p);

    // ---- LengthRegulator path ----
    embed_add_kernel<<<B_ * T_, 128>>>(p_x2, energy_t, ebins, etab, p_x2);
    cumsum_kernel<<<B_, 512>>>(duration, p_cum, p_ml, out + OFF_MELLEN);
    dim3 egrid(MAXL, B_);
    expand_kernel<<<egrid, 128>>>(p_x2, p_cum, p_ml, out + OFF_X, out + OFF_MASK);

    // ---- batched predictors ----
    dim3 cgrid(4, 2, 96);
    conv_bulk_kernel<<<cgrid, 256, CONV_SMEM>>>(
        p_xp, p_xp, p_x2p, p_w1p, c1b, p_h1p, (size_t)PSTR, 1);
    ln_packed_kernel<<<3 * 2048, 256>>>(p_h1p, g1, b1);
    conv_bulk_kernel<<<cgrid, 256, CONV_SMEM>>>(
        p_h1p, p_h1p + PSTR, p_h1p + 2 * (size_t)PSTR, p_w2p, c2b,
        p_h2, (size_t)(B_ * T_ * H_), 0);
    ln_head_kernel<<<3 * 2048, 256>>>(p_h2, g2, b2, lw, lb, out + OFF_LOGDUR);
}

// round 7
// speedup vs baseline: 1.6700x; 1.6700x over previous
#include <cuda_runtime.h>
#include <cuda_fp16.h>
#include <cstdint>

#define B_  32
#define T_  512
#define H_  512
#define NB  256
#define MAXL 2048

// packed fp16 activation rows: 32 data halves + pad -> 40 halves = 20 words
#define RW       20
#define APB_W    (514 * RW)          // words per (b,chunk)
#define A_BSTR_W (16 * APB_W)        // words per b
#define PSTR_W   (32 * A_BSTR_W)     // words per predictor
// packed fp16 weights: [pred 3][nt 4][stage 48][n 128][RW]
#define WSLOT_W  (128 * RW)
#define WNT_W    (48 * WSLOT_W)
#define WP_W     (3 * 4 * WNT_W)

// ---------------- scratch ----------------
__device__ __align__(256) uint32_t g_xp [32 * A_BSTR_W];
__device__ __align__(256) uint32_t g_x2p[32 * A_BSTR_W];
__device__ __align__(256) uint32_t g_h1p[3 * PSTR_W];
__device__ __align__(256) uint32_t g_w1p[WP_W];
__device__ __align__(256) uint32_t g_w2p[WP_W];
__device__ __align__(256) float g_h1[3 * B_ * T_ * H_];
__device__ __align__(256) float g_h2[3 * B_ * T_ * H_];
__device__ float g_x2 [B_ * T_ * H_];
__device__ int   g_cum[B_ * T_];
__device__ int   g_ml [B_];

__device__ __forceinline__ uint32_t smem_u32(const void* p) {
    uint32_t a;
    asm("{ .reg .u64 t; cvta.to.shared.u64 t, %1; cvt.u32.u64 %0, t; }" : "=r"(a) : "l"(p));
    return a;
}
__device__ __forceinline__ uint32_t h2pack(float x, float y) {
    __half2 h = __floats2half2_rn(x, y);
    return *reinterpret_cast<uint32_t*>(&h);
}

#define MBAR_INIT(a, n) \
    asm volatile("mbarrier.init.shared.b64 [%0], %1;" :: "r"(a), "r"(n) : "memory")
#define MBAR_EXPECT(a, bytes) \
    asm volatile("mbarrier.arrive.expect_tx.shared.b64 _, [%0], %1;" :: "r"(a), "r"(bytes) : "memory")
#define MBAR_WAIT(a, par) do {                                                   \
    uint32_t _m = (a); uint32_t _p = (par); uint32_t _d;                         \
    asm volatile("{ .reg .pred p;"                                               \
        " mbarrier.try_wait.parity.acquire.cta.shared::cta.b64 p, [%1], %2;"     \
        " selp.b32 %0, 1, 0, p; }" : "=r"(_d) : "r"(_m), "r"(_p) : "memory");    \
    if (!_d) {                                                                   \
        asm volatile("{ .reg .pred P1;"                                          \
            " WL_%=:"                                                            \
            " mbarrier.try_wait.parity.acquire.cta.shared::cta.b64 P1, [%0], %1, 0x989680;" \
            " @P1 bra.uni WD_%=;"                                                \
            " bra.uni WL_%=;"                                                    \
            " WD_%=: }" :: "r"(_m), "r"(_p) : "memory");                         \
    } } while (0)

__device__ __forceinline__ void bulk_ld(uint32_t dst, const void* src,
                                        uint32_t bytes, uint32_t mbar) {
    asm volatile(
        "cp.async.bulk.shared::cluster.global.mbarrier::complete_tx::bytes "
        "[%0], [%1], %2, [%3];"
        :: "r"(dst), "l"(src), "r"(bytes), "r"(mbar) : "memory");
}

// ---------------------------------------------------------------------------
// conv1d(K=3,pad=1) implicit GEMM, fp16 mma m16n8k16, bulk-copy pipeline.
// CTA 128x128, 8 warps in 4(M) x 2(N), warp tile 32x64, 2 CTAs/SM.
// ---------------------------------------------------------------------------
#define A_BYTES (130 * RW * 4)     // 10400
#define B_BYTES (WSLOT_W * 4)      // 10240
#define SA_OFF  64
#define SB_OFF  (64 + 2 * A_BYTES)
#define CONV_SMEM (SB_OFF + 3 * B_BYTES)   // 51584

extern __shared__ __align__(128) char csm[];

__global__ void __launch_bounds__(256, 2) conv_fp16_kernel(
    const uint32_t* __restrict__ in0, const uint32_t* __restrict__ in1,
    const uint32_t* __restrict__ in2, const uint32_t* __restrict__ wpk,
    const float* __restrict__ biasAll, float* __restrict__ outBase)
{
    const uint32_t sb = smem_u32(csm);
    const uint32_t* smw = (const uint32_t*)csm;
    const int tid  = threadIdx.x;
    const int lane = tid & 31, wid = tid >> 5;
    const int gr = lane >> 2, tc = lane & 3;
    const int wmm = wid & 3, wnn = wid >> 2;
    const int t0 = blockIdx.x * 128;
    const int n0 = blockIdx.y * 128;
    const int pred = blockIdx.z >> 5;
    const int b    = blockIdx.z & 31;

    const uint32_t* inP = (pred == 0) ? in0 : (pred == 1) ? in1 : in2;
    const uint32_t* aSrc = inP + (size_t)b * A_BSTR_W + (size_t)t0 * RW;
    const uint32_t* wB = wpk + (size_t)(pred * 4 + blockIdx.y) * WNT_W;
    const float* biasP = biasAll + pred * 512;

    if (tid == 0) {
#pragma unroll
        for (int i = 0; i < 5; i++) MBAR_INIT(sb + i * 8, 1);
    }
    __syncthreads();

#define ISSUE_A(c) do {                                                        \
    uint32_t mb = sb + ((c) & 1) * 8;                                          \
    MBAR_EXPECT(mb, A_BYTES);                                                  \
    bulk_ld(sb + SA_OFF + ((c) & 1) * A_BYTES, aSrc + (size_t)(c) * APB_W,     \
            A_BYTES, mb); } while (0)
#define ISSUE_B(s) do {                                                        \
    uint32_t mb = sb + 16 + ((s) % 3) * 8;                                     \
    MBAR_EXPECT(mb, B_BYTES);                                                  \
    bulk_ld(sb + SB_OFF + ((s) % 3) * B_BYTES, wB + (size_t)(s) * WSLOT_W,     \
            B_BYTES, mb); } while (0)

    if (tid == 0) { ISSUE_A(0); ISSUE_B(0); ISSUE_B(1); }

    float acc[2][8][4];
#pragma unroll
    for (int mi = 0; mi < 2; mi++)
#pragma unroll
        for (int ni = 0; ni < 8; ni++)
#pragma unroll
            for (int q = 0; q < 4; q++) acc[mi][ni][q] = 0.f;

    int c = 0, tap = 0;
    for (int s = 0; s < 48; ++s) {
        if (tid == 0) {
            if (tap == 0 && c + 1 < 16) ISSUE_A(c + 1);
            if (s + 2 < 48) ISSUE_B(s + 2);
        }
        MBAR_WAIT(sb + 16 + (s % 3) * 8, (s / 3) & 1);
        if (tap == 0) MBAR_WAIT(sb + (c & 1) * 8, (c >> 1) & 1);

        const uint32_t* SA = smw + (SA_OFF >> 2) + (c & 1) * (A_BYTES >> 2)
                           + (wmm * 32 + tap + gr) * RW;
        const uint32_t* SB = smw + (SB_OFF >> 2) + (s % 3) * (B_BYTES >> 2)
                           + (wnn * 64 + gr) * RW;
#pragma unroll
        for (int ks = 0; ks < 2; ks++) {
            uint32_t a[2][4], bb[8][2];
#pragma unroll
            for (int mi = 0; mi < 2; mi++) {
                const uint32_t* Am = SA + mi * 16 * RW + ks * 8 + tc;
                a[mi][0] = Am[0];
                a[mi][1] = Am[8 * RW];
                a[mi][2] = Am[4];
                a[mi][3] = Am[8 * RW + 4];
            }
#pragma unroll
            for (int ni = 0; ni < 8; ni++) {
                const uint32_t* Bm = SB + ni * 8 * RW + ks * 8 + tc;
                bb[ni][0] = Bm[0];
                bb[ni][1] = Bm[4];
            }
#pragma unroll
            for (int mi = 0; mi < 2; mi++)
#pragma unroll
                for (int ni = 0; ni < 8; ni++)
                    asm volatile(
                        "mma.sync.aligned.m16n8k16.row.col.f32.f16.f16.f32 "
                        "{%0,%1,%2,%3}, {%4,%5,%6,%7}, {%8,%9}, {%0,%1,%2,%3};"
                        : "+f"(acc[mi][ni][0]), "+f"(acc[mi][ni][1]),
                          "+f"(acc[mi][ni][2]), "+f"(acc[mi][ni][3])
                        : "r"(a[mi][0]), "r"(a[mi][1]), "r"(a[mi][2]), "r"(a[mi][3]),
                          "r"(bb[ni][0]), "r"(bb[ni][1]));
        }
        __syncthreads();
        if (++tap == 3) { tap = 0; ++c; }
    }

    // epilogue: bias + ReLU, linear fp32 out
    const int r0 = t0 + wmm * 32 + gr;
    const int c0 = n0 + wnn * 64 + tc * 2;
    float* ob = outBase + (size_t)pred * (B_ * T_ * H_) + (size_t)b * (512 * 512);
#pragma unroll
    for (int ni = 0; ni < 8; ni++) {
        int col = c0 + ni * 8;
        float b0 = __ldg(&biasP[col]), b1 = __ldg(&biasP[col + 1]);
#pragma unroll
        for (int mi = 0; mi < 2; mi++) {
            int row = r0 + mi * 16;
            float v0 = fmaxf(acc[mi][ni][0] + b0, 0.f);
            float v1 = fmaxf(acc[mi][ni][1] + b1, 0.f);
            float v2 = fmaxf(acc[mi][ni][2] + b0, 0.f);
            float v3 = fmaxf(acc[mi][ni][3] + b1, 0.f);
            *(float2*)&ob[(size_t)row * 512 + col]       = make_float2(v0, v1);
            *(float2*)&ob[(size_t)(row + 8) * 512 + col] = make_float2(v2, v3);
        }
    }
}

// pack weights fp32 [pred][tap][cin][cout] -> fp16 [pred][nt][st][n 128][RW]
__global__ void __launch_bounds__(256) pack_w_kernel(
    const float* __restrict__ w, uint32_t* __restrict__ wp)
{
    int g = blockIdx.x * 256 + threadIdx.x;           // WP_W = 1474560
    int wd = g % 20;
    int n  = (g / 20) % 128;
    int st = (g / 2560) % 48;
    int nt = (g / 122880) % 4;
    int pr = g / 491520;
    uint32_t o = 0;
    if (wd < 16) {
        int tap = st % 3, ch = st / 3, k = 2 * wd;
        const float* s = w + ((size_t)((pr * 3 + tap) * 512 + ch * 32 + k)) * 512
                       + nt * 128 + n;
        o = h2pack(s[0], s[512]);
    }
    wp[g] = o;
}

// pack tokens fp32 [b][t][512] -> fp16 [b][chunk][514][RW], halos zero
__global__ void __launch_bounds__(256) pack_tok_kernel(
    const float* __restrict__ src, uint32_t* __restrict__ dst)
{
    int g = blockIdx.x * 256 + threadIdx.x;           // 32*16*514*20 = 5255680
    int wd = g % 20;
    int r  = (g / 20) % 514;
    int x  = g / 10280;
    int ch = x & 15, b = x >> 4;
    uint32_t o = 0;
    if (r > 0 && r < 513 && wd < 16) {
        float2 v = *(const float2*)&src[(size_t)b * 262144 + (size_t)(r - 1) * 512
                                        + ch * 32 + 2 * wd];
        o = h2pack(v.x, v.y);
    }
    dst[g] = o;
}

// zero halo rows of x2p (buf 0) and h1p (bufs 1..3)
__global__ void __launch_bounds__(256) zero_halo_kernel(
    uint32_t* __restrict__ x2p, uint32_t* __restrict__ h1p)
{
    int g = blockIdx.x * 256 + threadIdx.x;           // 4*32*16*2*20 = 81920
    int wd = g % 20;
    int h  = (g / 20) & 1;
    int ch = (g / 40) & 15;
    int b  = (g / 640) & 31;
    int buf = g / 20480;
    size_t idx = ((size_t)(b * 16 + ch) * 514 + (h ? 513 : 0)) * RW + wd;
    if (buf == 0) x2p[idx] = 0;
    else          h1p[(size_t)(buf - 1) * PSTR_W + idx] = 0;
}

// LN: read linear fp32 h1, write packed fp16 h1p. 3 preds batched.
__global__ void __launch_bounds__(256) ln_pack_kernel(
    const float* __restrict__ h1, uint32_t* __restrict__ hp,
    const float* __restrict__ gAll, const float* __restrict__ btAll)
{
    int bid = blockIdx.x;                              // 3*2048
    int pred = bid >> 11;
    int tok = (bid & 2047) * 8 + (threadIdx.x >> 5);
    int lane = threadIdx.x & 31;
    const float* hr = h1 + (size_t)pred * (B_ * T_ * H_) + (size_t)tok * 512;
    const float* g  = gAll + pred * 512;
    const float* bt = btAll + pred * 512;
    float2 v[8];
    float s = 0.f, s2 = 0.f;
#pragma unroll
    for (int j = 0; j < 8; j++) {
        v[j] = *(const float2*)&hr[64 * j + 2 * lane];
        s += v[j].x + v[j].y;
        s2 += v[j].x * v[j].x + v[j].y * v[j].y;
    }
#pragma unroll
    for (int o = 16; o; o >>= 1) {
        s  += __shfl_xor_sync(0xffffffffu, s,  o);
        s2 += __shfl_xor_sync(0xffffffffu, s2, o);
    }
    float mean = s * (1.f / 512.f);
    float var  = s2 * (1.f / 512.f) - mean * mean;
    float rs   = rsqrtf(var + 1e-5f);
    int b = tok >> 9, t = tok & 511;
    uint32_t* dst = hp + (size_t)pred * PSTR_W + (size_t)b * A_BSTR_W;
#pragma unroll
    for (int j = 0; j < 8; j++) {
        int f0 = 64 * j + 2 * lane;
        float y0 = (v[j].x - mean) * rs * g[f0]     + bt[f0];
        float y1 = (v[j].y - mean) * rs * g[f0 + 1] + bt[f0 + 1];
        int ch = 2 * j + (lane >> 4);
        dst[((size_t)ch * 514 + t + 1) * RW + (lane & 15)] = h2pack(y0, y1);
    }
}

// LN + linear head on linear fp32 h2; 3 preds batched.
__global__ void __launch_bounds__(256) ln_head_kernel(
    const float* __restrict__ h2, const float* __restrict__ gAll,
    const float* __restrict__ btAll, const float* __restrict__ lwAll,
    const float* __restrict__ lb, float* __restrict__ outPred)
{
    int bid = blockIdx.x;
    int pred = bid >> 11;
    int token = (bid & 2047) * 8 + (threadIdx.x >> 5);
    int lane  = threadIdx.x & 31;
    const float* hr = h2 + (size_t)pred * (B_ * T_ * H_) + (size_t)token * 512;
    const float* g  = gAll + pred * 512;
    const float* bt = btAll + pred * 512;
    const float* lw = lwAll + pred * 512;
    float v[16], s = 0.f, s2 = 0.f;
#pragma unroll
    for (int k = 0; k < 16; k++) {
        v[k] = hr[lane + 32 * k];
        s += v[k]; s2 += v[k] * v[k];
    }
#pragma unroll
    for (int o = 16; o; o >>= 1) {
        s  += __shfl_xor_sync(0xffffffffu, s,  o);
        s2 += __shfl_xor_sync(0xffffffffu, s2, o);
    }
    float mean = s * (1.f / 512.f);
    float var  = s2 * (1.f / 512.f) - mean * mean;
    float rs   = rsqrtf(var + 1e-5f);
    float dot = 0.f;
#pragma unroll
    for (int k = 0; k < 16; k++) {
        int f = lane + 32 * k;
        dot += ((v[k] - mean) * rs * g[f] + bt[f]) * lw[f];
    }
#pragma unroll
    for (int o = 16; o; o >>= 1) dot += __shfl_xor_sync(0xffffffffu, dot, o);
    if (lane == 0) outPred[(size_t)pred * (B_ * T_) + token] = dot + lb[pred];
}

// embed add, fp32 out + fp16 packed out (pitch path)
__global__ void __launch_bounds__(128) embed_add_pack_kernel(
    const float* __restrict__ xin, const float* __restrict__ target,
    const float* __restrict__ bins, const float* __restrict__ table,
    float* __restrict__ xout, uint32_t* __restrict__ xpk)
{
    int token = blockIdx.x;
    int b = token >> 9, t = token & 511;
    float tv = target[token];
    int lo = 0, hi = NB - 1;
    while (lo < hi) {
        int mid = (lo + hi) >> 1;
        if (bins[mid] < tv) lo = mid + 1; else hi = mid;
    }
    int i = threadIdx.x;
    float4 a = ((const float4*)(xin + (size_t)token * H_))[i];
    float4 c = ((const float4*)(table + (size_t)lo * H_))[i];
    float4 r = make_float4(a.x + c.x, a.y + c.y, a.z + c.z, a.w + c.w);
    ((float4*)(xout + (size_t)token * H_))[i] = r;
    int ch = i >> 3, w = (i & 7) * 2;
    uint32_t* d = xpk + ((size_t)(b * 16 + ch) * 514 + t + 1) * RW + w;
    d[0] = h2pack(r.x, r.y);
    d[1] = h2pack(r.z, r.w);
}

// plain embed add (energy path, in place)
__global__ void __launch_bounds__(128) embed_add_kernel(
    const float* __restrict__ xin, const float* __restrict__ target,
    const float* __restrict__ bins, const float* __restrict__ table,
    float* __restrict__ xout)
{
    int token = blockIdx.x;
    float tv = target[token];
    int lo = 0, hi = NB - 1;
    while (lo < hi) {
        int mid = (lo + hi) >> 1;
        if (bins[mid] < tv) lo = mid + 1; else hi = mid;
    }
    int i = threadIdx.x;
    float4 a = ((const float4*)(xin + (size_t)token * H_))[i];
    float4 c = ((const float4*)(table + (size_t)lo * H_))[i];
    ((float4*)(xout + (size_t)token * H_))[i] =
        make_float4(a.x + c.x, a.y + c.y, a.z + c.z, a.w + c.w);
}

__global__ void __launch_bounds__(512) cumsum_kernel(
    const int* __restrict__ dur, int* __restrict__ cum,
    int* __restrict__ mellen, float* __restrict__ out_mellen)
{
    __shared__ int s[512];
    int b = blockIdx.x, t = threadIdx.x;
    s[t] = dur[b * T_ + t];
    __syncthreads();
    for (int off = 1; off < 512; off <<= 1) {
        int v = (t >= off) ? s[t - off] : 0;
        __syncthreads();
        s[t] += v;
        __syncthreads();
    }
    cum[b * T_ + t] = s[t];
    if (t == 511) {
        int ml = s[511] < MAXL ? s[511] : MAXL;
        mellen[b] = ml;
        out_mellen[b] = (float)ml;
    }
}

__global__ void __launch_bounds__(128) expand_kernel(
    const float* __restrict__ x3, const int* __restrict__ cum,
    const int* __restrict__ mellen, float* __restrict__ outx,
    float* __restrict__ outmask)
{
    int frame = blockIdx.x, b = blockIdx.y;
    int ml = mellen[b];
    float* orow = outx + ((size_t)b * MAXL + frame) * H_;
    bool masked = frame >= ml;
    if (threadIdx.x == 0) outmask[b * MAXL + frame] = masked ? 1.0f : 0.0f;
    if (masked) {
        ((float4*)orow)[threadIdx.x] = make_float4(0, 0, 0, 0);
        return;
    }
    const int* cb = cum + b * T_;
    int lo = 0, hi = T_;
    while (lo < hi) {
        int mid = (lo + hi) >> 1;
        if (cb[mid] <= frame) lo = mid + 1; else hi = mid;
    }
    if (lo > T_ - 1) lo = T_ - 1;
    ((float4*)orow)[threadIdx.x] =
        ((const float4*)(x3 + ((size_t)b * T_ + lo) * H_))[threadIdx.x];
}

extern "C" void kernel_launch(void* const* d_in, const int* in_sizes, int n_in,
                              void* d_out, int out_size)
{
    const float* x        = (const float*)d_in[0];
    const int*   duration = (const int*)  d_in[2];
    const float* pitch_t  = (const float*)d_in[3];
    const float* energy_t = (const float*)d_in[4];
    const float* c1w = (const float*)d_in[5];
    const float* c1b = (const float*)d_in[6];
    const float* g1  = (const float*)d_in[7];
    const float* b1  = (const float*)d_in[8];
    const float* c2w = (const float*)d_in[9];
    const float* c2b = (const float*)d_in[10];
    const float* g2  = (const float*)d_in[11];
    const float* b2  = (const float*)d_in[12];
    const float* lw  = (const float*)d_in[13];
    const float* lb  = (const float*)d_in[14];
    const float* pbins = (const float*)d_in[15];
    const float* ebins = (const float*)d_in[16];
    const float* ptab  = (const float*)d_in[17];
    const float* etab  = (const float*)d_in[18];

    float* out = (float*)d_out;
    const size_t OFF_LOGDUR = (size_t)B_ * MAXL * H_;
    const size_t OFF_MELLEN = OFF_LOGDUR + 3 * (size_t)B_ * T_;
    const size_t OFF_MASK   = OFF_MELLEN + B_;

    uint32_t *p_xp, *p_x2p, *p_h1p, *p_w1p, *p_w2p;
    float *p_h1, *p_h2, *p_x2;
    int *p_cum, *p_ml;
    cudaGetSymbolAddress((void**)&p_xp,  g_xp);
    cudaGetSymbolAddress((void**)&p_x2p, g_x2p);
    cudaGetSymbolAddress((void**)&p_h1p, g_h1p);
    cudaGetSymbolAddress((void**)&p_w1p, g_w1p);
    cudaGetSymbolAddress((void**)&p_w2p, g_w2p);
    cudaGetSymbolAddress((void**)&p_h1,  g_h1);
    cudaGetSymbolAddress((void**)&p_h2,  g_h2);
    cudaGetSymbolAddress((void**)&p_x2,  g_x2);
    cudaGetSymbolAddress((void**)&p_cum, g_cum);
    cudaGetSymbolAddress((void**)&p_ml,  g_ml);

    cudaFuncSetAttribute(conv_fp16_kernel,
                         cudaFuncAttributeMaxDynamicSharedMemorySize, CONV_SMEM);

    // ---- prep ----
    pack_w_kernel<<<WP_W / 256, 256>>>(c1w, p_w1p);
    pack_w_kernel<<<WP_W / 256, 256>>>(c2w, p_w2p);
    pack_tok_kernel<<<(32 * 16 * 514 * 20) / 256, 256>>>(x, p_xp);
    embed_add_pack_kernel<<<B_ * T_, 128>>>(x, pitch_t, pbins, ptab, p_x2, p_x2p);
    zero_halo_kernel<<<320, 256>>>(p_x2p, p_h1p);

    // ---- LengthRegulator path ----
    embed_add_kernel<<<B_ * T_, 128>>>(p_x2, energy_t, ebins, etab, p_x2);
    cumsum_kernel<<<B_, 512>>>(duration, p_cum, p_ml, out + OFF_MELLEN);
    dim3 egrid(MAXL, B_);
    expand_kernel<<<egrid, 128>>>(p_x2, p_cum, p_ml, out, out + OFF_MASK);

    // ---- batched predictors ----
    dim3 cgrid(4, 4, 96);
    conv_fp16_kernel<<<cgrid, 256, CONV_SMEM>>>(
        p_xp, p_xp, p_x2p, p_w1p, c1b, p_h1);
    ln_pack_kernel<<<3 * 2048, 256>>>(p_h1, p_h1p, g1, b1);
    conv_fp16_kernel<<<cgrid, 256, CONV_SMEM>>>(
        p_h1p, p_h1p + PSTR_W, p_h1p + 2 * (size_t)PSTR_W, p_w2p, c2b, p_h2);
    ln_head_kernel<<<3 * 2048, 256>>>(p_h2, g2, b2, lw, lb, out + OFF_LOGDUR);
}

// round 8
// speedup vs baseline: 1.8456x; 1.1052x over previous
#include <cuda_runtime.h>
#include <cuda_fp16.h>
#include <cstdint>

#define B_  32
#define T_  512
#define H_  512
#define NB  256
#define MAXL 2048

// packed fp16 activation rows: 64 data halves (32 words) + pad -> 36 words
#define RW       36
#define APB_W    (514 * RW)          // words per (b,chunk);  8 chunks of 64ch
#define A_BSTR_W (8 * APB_W)         // words per b
#define PSTR_W   (32 * A_BSTR_W)     // words per predictor
// packed fp16 weights: [pred 3][nt 4][stage 24][n 128][RW]
#define WSLOT_W  (128 * RW)
#define WNT_W    (24 * WSLOT_W)
#define WP_W     (3 * 4 * WNT_W)

// ---------------- scratch ----------------
__device__ __align__(256) uint32_t g_xp [32 * A_BSTR_W];
__device__ __align__(256) uint32_t g_x2p[32 * A_BSTR_W];
__device__ __align__(256) uint32_t g_h1p[3 * PSTR_W];
__device__ __align__(256) uint32_t g_w1p[WP_W];
__device__ __align__(256) uint32_t g_w2p[WP_W];
__device__ __align__(256) uint32_t g_h2 [3 * B_ * T_ * 256];  // fp16 linear
__device__ float g_x2 [B_ * T_ * H_];
__device__ int   g_cum[B_ * T_];
__device__ int   g_ml [B_];

__device__ __forceinline__ uint32_t smem_u32(const void* p) {
    uint32_t a;
    asm("{ .reg .u64 t; cvta.to.shared.u64 t, %1; cvt.u32.u64 %0, t; }" : "=r"(a) : "l"(p));
    return a;
}
__device__ __forceinline__ uint32_t h2pack(float x, float y) {
    __half2 h = __floats2half2_rn(x, y);
    return *reinterpret_cast<uint32_t*>(&h);
}
__device__ __forceinline__ float2 h2unpack(uint32_t u) {
    __half2 h = *reinterpret_cast<__half2*>(&u);
    return __half22float2(h);
}

#define MBAR_INIT(a, n) \
    asm volatile("mbarrier.init.shared.b64 [%0], %1;" :: "r"(a), "r"(n) : "memory")
#define MBAR_EXPECT(a, bytes) \
    asm volatile("mbarrier.arrive.expect_tx.shared.b64 _, [%0], %1;" :: "r"(a), "r"(bytes) : "memory")
#define MBAR_WAIT(a, par) do {                                                   \
    uint32_t _m = (a); uint32_t _p = (par); uint32_t _d;                         \
    asm volatile("{ .reg .pred p;"                                               \
        " mbarrier.try_wait.parity.acquire.cta.shared::cta.b64 p, [%1], %2;"     \
        " selp.b32 %0, 1, 0, p; }" : "=r"(_d) : "r"(_m), "r"(_p) : "memory");    \
    if (!_d) {                                                                   \
        asm volatile("{ .reg .pred P1;"                                          \
            " WL_%=:"                                                            \
            " mbarrier.try_wait.parity.acquire.cta.shared::cta.b64 P1, [%0], %1, 0x989680;" \
            " @P1 bra.uni WD_%=;"                                                \
            " bra.uni WL_%=;"                                                    \
            " WD_%=: }" :: "r"(_m), "r"(_p) : "memory");                         \
    } } while (0)

__device__ __forceinline__ void bulk_ld(uint32_t dst, const void* src,
                                        uint32_t bytes, uint32_t mbar) {
    asm volatile(
        "cp.async.bulk.shared::cluster.global.mbarrier::complete_tx::bytes "
        "[%0], [%1], %2, [%3];"
        :: "r"(dst), "l"(src), "r"(bytes), "r"(mbar) : "memory");
}

// ---------------------------------------------------------------------------
// conv1d(K=3,pad=1) implicit GEMM, fp16 mma m16n8k16, 24-stage K=64 pipeline.
// CTA 128x128, 8 warps 4(M) x 2(N), warp tile 32x64, 2 CTAs/SM.
// smem: 64 mbar | A 2x18720 | B 3x18432 = 92800 B
// ---------------------------------------------------------------------------
#define A_BYTES (130 * RW * 4)     // 18720
#define B_BYTES (WSLOT_W * 4)      // 18432
#define SA_OFF  64
#define SB_OFF  (64 + 2 * A_BYTES)
#define CONV_SMEM (SB_OFF + 3 * B_BYTES)

extern __shared__ __align__(128) char csm[];

__global__ void __launch_bounds__(256, 2) conv_fp16_kernel(
    const uint32_t* __restrict__ in0, const uint32_t* __restrict__ in1,
    const uint32_t* __restrict__ in2, const uint32_t* __restrict__ wpk,
    const float* __restrict__ biasAll, uint32_t* __restrict__ outBase,
    int packedOut)
{
    const uint32_t sb = smem_u32(csm);
    const uint32_t* smw = (const uint32_t*)csm;
    const int tid  = threadIdx.x;
    const int lane = tid & 31, wid = tid >> 5;
    const int gr = lane >> 2, tc = lane & 3;
    const int wmm = wid & 3, wnn = wid >> 2;
    const int t0 = blockIdx.x * 128;
    const int n0 = blockIdx.y * 128;
    const int pred = blockIdx.z >> 5;
    const int b    = blockIdx.z & 31;

    const uint32_t* inP = (pred == 0) ? in0 : (pred == 1) ? in1 : in2;
    const uint32_t* aSrc = inP + (size_t)b * A_BSTR_W + (size_t)t0 * RW;
    const uint32_t* wB = wpk + (size_t)(pred * 4 + blockIdx.y) * WNT_W;
    const float* biasP = biasAll + pred * 512;

    if (tid == 0) {
#pragma unroll
        for (int i = 0; i < 5; i++) MBAR_INIT(sb + i * 8, 1);
    }
    __syncthreads();

#define ISSUE_A(c) do {                                                        \
    uint32_t mb = sb + ((c) & 1) * 8;                                          \
    MBAR_EXPECT(mb, A_BYTES);                                                  \
    bulk_ld(sb + SA_OFF + ((c) & 1) * A_BYTES, aSrc + (size_t)(c) * APB_W,     \
            A_BYTES, mb); } while (0)
#define ISSUE_B(s) do {                                                        \
    uint32_t mb = sb + 16 + ((s) % 3) * 8;                                     \
    MBAR_EXPECT(mb, B_BYTES);                                                  \
    bulk_ld(sb + SB_OFF + ((s) % 3) * B_BYTES, wB + (size_t)(s) * WSLOT_W,     \
            B_BYTES, mb); } while (0)

    if (tid == 0) { ISSUE_A(0); ISSUE_B(0); ISSUE_B(1); }

    float acc[2][8][4];
#pragma unroll
    for (int mi = 0; mi < 2; mi++)
#pragma unroll
        for (int ni = 0; ni < 8; ni++)
#pragma unroll
            for (int q = 0; q < 4; q++) acc[mi][ni][q] = 0.f;

    int c = 0, tap = 0;
    for (int s = 0; s < 24; ++s) {
        if (tid == 0) {
            if (tap == 0 && c + 1 < 8) ISSUE_A(c + 1);
            if (s + 2 < 24) ISSUE_B(s + 2);
        }
        MBAR_WAIT(sb + 16 + (s % 3) * 8, (s / 3) & 1);
        if (tap == 0) MBAR_WAIT(sb + (c & 1) * 8, (c >> 1) & 1);

        const uint32_t* SA = smw + (SA_OFF >> 2) + (c & 1) * (A_BYTES >> 2)
                           + (wmm * 32 + tap + gr) * RW;
        const uint32_t* SB = smw + (SB_OFF >> 2) + (s % 3) * (B_BYTES >> 2)
                           + (wnn * 64 + gr) * RW;
#pragma unroll
        for (int ks = 0; ks < 4; ks++) {
            uint32_t a[2][4], bb[8][2];
#pragma unroll
            for (int mi = 0; mi < 2; mi++) {
                const uint32_t* Am = SA + mi * 16 * RW + ks * 8 + tc;
                a[mi][0] = Am[0];
                a[mi][1] = Am[8 * RW];
                a[mi][2] = Am[4];
                a[mi][3] = Am[8 * RW + 4];
            }
#pragma unroll
            for (int ni = 0; ni < 8; ni++) {
                const uint32_t* Bm = SB + ni * 8 * RW + ks * 8 + tc;
                bb[ni][0] = Bm[0];
                bb[ni][1] = Bm[4];
            }
#pragma unroll
            for (int mi = 0; mi < 2; mi++)
#pragma unroll
                for (int ni = 0; ni < 8; ni++)
                    asm volatile(
                        "mma.sync.aligned.m16n8k16.row.col.f32.f16.f16.f32 "
                        "{%0,%1,%2,%3}, {%4,%5,%6,%7}, {%8,%9}, {%0,%1,%2,%3};"
                        : "+f"(acc[mi][ni][0]), "+f"(acc[mi][ni][1]),
                          "+f"(acc[mi][ni][2]), "+f"(acc[mi][ni][3])
                        : "r"(a[mi][0]), "r"(a[mi][1]), "r"(a[mi][2]), "r"(a[mi][3]),
                          "r"(bb[ni][0]), "r"(bb[ni][1]));
        }
        __syncthreads();
        if (++tap == 3) { tap = 0; ++c; }
    }

    // epilogue: bias + ReLU, fp16 out
    const int r0 = t0 + wmm * 32 + gr;
    const int c0 = n0 + wnn * 64 + tc * 2;
    if (packedOut) {
        // packed layout [ch 8][514][RW]
        uint32_t* ob = outBase + (size_t)pred * PSTR_W + (size_t)b * A_BSTR_W;
#pragma unroll
        for (int ni = 0; ni < 8; ni++) {
            int col = c0 + ni * 8;
            int ch = col >> 6, wrd = (col & 63) >> 1;
            float b0 = __ldg(&biasP[col]), b1 = __ldg(&biasP[col + 1]);
            uint32_t* cb = ob + (size_t)ch * APB_W + wrd;
#pragma unroll
            for (int mi = 0; mi < 2; mi++) {
                int row = r0 + mi * 16;
                cb[(size_t)(row + 1) * RW] =
                    h2pack(fmaxf(acc[mi][ni][0] + b0, 0.f),
                           fmaxf(acc[mi][ni][1] + b1, 0.f));
                cb[(size_t)(row + 9) * RW] =
                    h2pack(fmaxf(acc[mi][ni][2] + b0, 0.f),
                           fmaxf(acc[mi][ni][3] + b1, 0.f));
            }
        }
    } else {
        // linear fp16 rows: 256 words per token
        uint32_t* ob = outBase + (size_t)pred * (B_ * T_ * 256)
                     + (size_t)b * (512 * 256);
#pragma unroll
        for (int ni = 0; ni < 8; ni++) {
            int col = c0 + ni * 8;
            float b0 = __ldg(&biasP[col]), b1 = __ldg(&biasP[col + 1]);
#pragma unroll
            for (int mi = 0; mi < 2; mi++) {
                int row = r0 + mi * 16;
                ob[(size_t)row * 256 + (col >> 1)] =
                    h2pack(fmaxf(acc[mi][ni][0] + b0, 0.f),
                           fmaxf(acc[mi][ni][1] + b1, 0.f));
                ob[(size_t)(row + 8) * 256 + (col >> 1)] =
                    h2pack(fmaxf(acc[mi][ni][2] + b0, 0.f),
                           fmaxf(acc[mi][ni][3] + b1, 0.f));
            }
        }
    }
}

// pack weights fp32 [pred][tap][cin][cout] -> fp16 [pred][nt][st 24][n 128][RW]
__global__ void __launch_bounds__(256) pack_w_kernel(
    const float* __restrict__ w, uint32_t* __restrict__ wp)
{
    int g = blockIdx.x * 256 + threadIdx.x;           // WP_W = 1327104
    int wd = g % RW;
    int n  = (g / RW) % 128;
    int st = (g / WSLOT_W) % 24;
    int nt = (g / WNT_W) % 4;
    int pr = g / (4 * WNT_W);
    uint32_t o = 0;
    if (wd < 32) {
        int tap = st % 3, ch = st / 3, k = ch * 64 + 2 * wd;
        const float* s = w + ((size_t)((pr * 3 + tap) * 512 + k)) * 512
                       + nt * 128 + n;
        o = h2pack(s[0], s[512]);
    }
    wp[g] = o;
}

// pack tokens fp32 [b][t][512] -> fp16 [b][ch 8][514][RW], halos zero
__global__ void __launch_bounds__(256) pack_tok_kernel(
    const float* __restrict__ src, uint32_t* __restrict__ dst)
{
    int g = blockIdx.x * 256 + threadIdx.x;           // 32*8*514*36 = 4741632
    int wd = g % RW;
    int r  = (g / RW) % 514;
    int x  = g / APB_W;
    int ch = x & 7, b = x >> 3;
    uint32_t o = 0;
    if (r > 0 && r < 513 && wd < 32) {
        float2 v = *(const float2*)&src[(size_t)b * 262144 + (size_t)(r - 1) * 512
                                        + ch * 64 + 2 * wd];
        o = h2pack(v.x, v.y);
    }
    dst[g] = o;
}

// zero halo rows of x2p (buf 0) and h1p (bufs 1..3)
__global__ void __launch_bounds__(256) zero_halo_kernel(
    uint32_t* __restrict__ x2p, uint32_t* __restrict__ h1p)
{
    int g = blockIdx.x * 256 + threadIdx.x;           // 4*32*8*2*36 = 73728
    int wd = g % RW;
    int h  = (g / RW) & 1;
    int ch = (g / (2 * RW)) & 7;
    int b  = (g / (16 * RW)) & 31;
    int buf = g / (512 * RW);
    size_t idx = ((size_t)(b * 8 + ch) * 514 + (h ? 513 : 0)) * RW + wd;
    if (buf == 0) x2p[idx] = 0;
    else          h1p[(size_t)(buf - 1) * PSTR_W + idx] = 0;
}

// in-place LN on packed fp16 h1p. warp per token, 3 preds batched.
__global__ void __launch_bounds__(256) ln_packed_kernel(
    uint32_t* __restrict__ hp, const float* __restrict__ gAll,
    const float* __restrict__ btAll)
{
    int bid = blockIdx.x;                              // 3*2048
    int pred = bid >> 11;
    int tok = (bid & 2047) * 8 + (threadIdx.x >> 5);
    int lane = threadIdx.x & 31;
    int b = tok >> 9, t = tok & 511;
    uint32_t* base = hp + (size_t)pred * PSTR_W + (size_t)b * A_BSTR_W
                   + (size_t)(t + 1) * RW + lane;
    const float* g  = gAll + pred * 512;
    const float* bt = btAll + pred * 512;
    float2 v[8];
    float s = 0.f, s2 = 0.f;
#pragma unroll
    for (int j = 0; j < 8; j++) {
        v[j] = h2unpack(base[(size_t)j * APB_W]);
        s += v[j].x + v[j].y;
        s2 += v[j].x * v[j].x + v[j].y * v[j].y;
    }
#pragma unroll
    for (int o = 16; o; o >>= 1) {
        s  += __shfl_xor_sync(0xffffffffu, s,  o);
        s2 += __shfl_xor_sync(0xffffffffu, s2, o);
    }
    float mean = s * (1.f / 512.f);
    float var  = s2 * (1.f / 512.f) - mean * mean;
    float rs   = rsqrtf(var + 1e-5f);
#pragma unroll
    for (int j = 0; j < 8; j++) {
        int f = j * 64 + 2 * lane;
        base[(size_t)j * APB_W] =
            h2pack((v[j].x - mean) * rs * g[f] + bt[f],
                   (v[j].y - mean) * rs * g[f + 1] + bt[f + 1]);
    }
}

// LN + linear head on linear fp16 h2; 3 preds batched.
__global__ void __launch_bounds__(256) ln_head_kernel(
    const uint32_t* __restrict__ h2, const float* __restrict__ gAll,
    const float* __restrict__ btAll, const float* __restrict__ lwAll,
    const float* __restrict__ lb, float* __restrict__ outPred)
{
    int bid = blockIdx.x;
    int pred = bid >> 11;
    int token = (bid & 2047) * 8 + (threadIdx.x >> 5);
    int lane  = threadIdx.x & 31;
    const uint32_t* hr = h2 + (size_t)pred * (B_ * T_ * 256) + (size_t)token * 256;
    const float* g  = gAll + pred * 512;
    const float* bt = btAll + pred * 512;
    const float* lw = lwAll + pred * 512;
    float2 v[8];
    float s = 0.f, s2 = 0.f;
#pragma unroll
    for (int j = 0; j < 8; j++) {
        v[j] = h2unpack(hr[lane + 32 * j]);
        s += v[j].x + v[j].y;
        s2 += v[j].x * v[j].x + v[j].y * v[j].y;
    }
#pragma unroll
    for (int o = 16; o; o >>= 1) {
        s  += __shfl_xor_sync(0xffffffffu, s,  o);
        s2 += __shfl_xor_sync(0xffffffffu, s2, o);
    }
    float mean = s * (1.f / 512.f);
    float var  = s2 * (1.f / 512.f) - mean * mean;
    float rs   = rsqrtf(var + 1e-5f);
    float dot = 0.f;
#pragma unroll
    for (int j = 0; j < 8; j++) {
        int f = 2 * (lane + 32 * j);
        dot += ((v[j].x - mean) * rs * g[f] + bt[f]) * lw[f];
        dot += ((v[j].y - mean) * rs * g[f + 1] + bt[f + 1]) * lw[f + 1];
    }
#pragma unroll
    for (int o = 16; o; o >>= 1) dot += __shfl_xor_sync(0xffffffffu, dot, o);
    if (lane == 0) outPred[(size_t)pred * (B_ * T_) + token] = dot + lb[pred];
}

// embed add, fp32 out + fp16 packed out (pitch path)
__global__ void __launch_bounds__(128) embed_add_pack_kernel(
    const float* __restrict__ xin, const float* __restrict__ target,
    const float* __restrict__ bins, const float* __restrict__ table,
    float* __restrict__ xout, uint32_t* __restrict__ xpk)
{
    int token = blockIdx.x;
    int b = token >> 9, t = token & 511;
    float tv = target[token];
    int lo = 0, hi = NB - 1;
    while (lo < hi) {
        int mid = (lo + hi) >> 1;
        if (bins[mid] < tv) lo = mid + 1; else hi = mid;
    }
    int i = threadIdx.x;
    float4 a = ((const float4*)(xin + (size_t)token * H_))[i];
    float4 c = ((const float4*)(table + (size_t)lo * H_))[i];
    float4 r = make_float4(a.x + c.x, a.y + c.y, a.z + c.z, a.w + c.w);
    ((float4*)(xout + (size_t)token * H_))[i] = r;
    int ch = i >> 4, w = (i & 15) * 2;
    uint32_t* d = xpk + ((size_t)(b * 8 + ch) * 514 + t + 1) * RW + w;
    d[0] = h2pack(r.x, r.y);
    d[1] = h2pack(r.z, r.w);
}

// plain embed add (energy path, in place)
__global__ void __launch_bounds__(128) embed_add_kernel(
    const float* __restrict__ xin, const float* __restrict__ target,
    const float* __restrict__ bins, const float* __restrict__ table,
    float* __restrict__ xout)
{
    int token = blockIdx.x;
    float tv = target[token];
    int lo = 0, hi = NB - 1;
    while (lo < hi) {
        int mid = (lo + hi) >> 1;
        if (bins[mid] < tv) lo = mid + 1; else hi = mid;
    }
    int i = threadIdx.x;
    float4 a = ((const float4*)(xin + (size_t)token * H_))[i];
    float4 c = ((const float4*)(table + (size_t)lo * H_))[i];
    ((float4*)(xout + (size_t)token * H_))[i] =
        make_float4(a.x + c.x, a.y + c.y, a.z + c.z, a.w + c.w);
}

__global__ void __launch_bounds__(512) cumsum_kernel(
    const int* __restrict__ dur, int* __restrict__ cum,
    int* __restrict__ mellen, float* __restrict__ out_mellen)
{
    __shared__ int s[512];
    int b = blockIdx.x, t = threadIdx.x;
    s[t] = dur[b * T_ + t];
    __syncthreads();
    for (int off = 1; off < 512; off <<= 1) {
        int v = (t >= off) ? s[t - off] : 0;
        __syncthreads();
        s[t] += v;
        __syncthreads();
    }
    cum[b * T_ + t] = s[t];
    if (t == 511) {
        int ml = s[511] < MAXL ? s[511] : MAXL;
        mellen[b] = ml;
        out_mellen[b] = (float)ml;
    }
}

__global__ void __launch_bounds__(128) expand_kernel(
    const float* __restrict__ x3, const int* __restrict__ cum,
    const int* __restrict__ mellen, float* __restrict__ outx,
    float* __restrict__ outmask)
{
    int frame = blockIdx.x, b = blockIdx.y;
    int ml = mellen[b];
    float* orow = outx + ((size_t)b * MAXL + frame) * H_;
    bool masked = frame >= ml;
    if (threadIdx.x == 0) outmask[b * MAXL + frame] = masked ? 1.0f : 0.0f;
    if (masked) {
        ((float4*)orow)[threadIdx.x] = make_float4(0, 0, 0, 0);
        return;
    }
    const int* cb = cum + b * T_;
    int lo = 0, hi = T_;
    while (lo < hi) {
        int mid = (lo + hi) >> 1;
        if (cb[mid] <= frame) lo = mid + 1; else hi = mid;
    }
    if (lo > T_ - 1) lo = T_ - 1;
    ((float4*)orow)[threadIdx.x] =
        ((const float4*)(x3 + ((size_t)b * T_ + lo) * H_))[threadIdx.x];
}

extern "C" void kernel_launch(void* const* d_in, const int* in_sizes, int n_in,
                              void* d_out, int out_size)
{
    const float* x        = (const float*)d_in[0];
    const int*   duration = (const int*)  d_in[2];
    const float* pitch_t  = (const float*)d_in[3];
    const float* energy_t = (const float*)d_in[4];
    const float* c1w = (const float*)d_in[5];
    const float* c1b = (const float*)d_in[6];
    const float* g1  = (const float*)d_in[7];
    const float* b1  = (const float*)d_in[8];
    const float* c2w = (const float*)d_in[9];
    const float* c2b = (const float*)d_in[10];
    const float* g2  = (const float*)d_in[11];
    const float* b2  = (const float*)d_in[12];
    const float* lw  = (const float*)d_in[13];
    const float* lb  = (const float*)d_in[14];
    const float* pbins = (const float*)d_in[15];
    const float* ebins = (const float*)d_in[16];
    const float* ptab  = (const float*)d_in[17];
    const float* etab  = (const float*)d_in[18];

    float* out = (float*)d_out;
    const size_t OFF_LOGDUR = (size_t)B_ * MAXL * H_;
    const size_t OFF_MELLEN = OFF_LOGDUR + 3 * (size_t)B_ * T_;
    const size_t OFF_MASK   = OFF_MELLEN + B_;

    uint32_t *p_xp, *p_x2p, *p_h1p, *p_w1p, *p_w2p, *p_h2;
    float *p_x2;
    int *p_cum, *p_ml;
    cudaGetSymbolAddress((void**)&p_xp,  g_xp);
    cudaGetSymbolAddress((void**)&p_x2p, g_x2p);
    cudaGetSymbolAddress((void**)&p_h1p, g_h1p);
    cudaGetSymbolAddress((void**)&p_w1p, g_w1p);
    cudaGetSymbolAddress((void**)&p_w2p, g_w2p);
    cudaGetSymbolAddress((void**)&p_h2,  g_h2);
    cudaGetSymbolAddress((void**)&p_x2,  g_x2);
    cudaGetSymbolAddress((void**)&p_cum, g_cum);
    cudaGetSymbolAddress((void**)&p_ml,  g_ml);

    cudaFuncSetAttribute(conv_fp16_kernel,
                         cudaFuncAttributeMaxDynamicSharedMemorySize, CONV_SMEM);

    // ---- prep ----
    pack_w_kernel<<<WP_W / 256, 256>>>(c1w, p_w1p);
    pack_w_kernel<<<WP_W / 256, 256>>>(c2w, p_w2p);
    pack_tok_kernel<<<(32 * A_BSTR_W) / 256, 256>>>(x, p_xp);
    embed_add_pack_kernel<<<B_ * T_, 128>>>(x, pitch_t, pbins, ptab, p_x2, p_x2p);
    zero_halo_kernel<<<288, 256>>>(p_x2p, p_h1p);

    // ---- LengthRegulator path ----
    embed_add_kernel<<<B_ * T_, 128>>>(p_x2, energy_t, ebins, etab, p_x2);
    cumsum_kernel<<<B_, 512>>>(duration, p_cum, p_ml, out + OFF_MELLEN);
    dim3 egrid(MAXL, B_);
    expand_kernel<<<egrid, 128>>>(p_x2, p_cum, p_ml, out, out + OFF_MASK);

    // ---- batched predictors ----
    dim3 cgrid(4, 4, 96);
    conv_fp16_kernel<<<cgrid, 256, CONV_SMEM>>>(
        p_xp, p_xp, p_x2p, p_w1p, c1b, p_h1p, 1);
    ln_packed_kernel<<<3 * 2048, 256>>>(p_h1p, g1, b1);
    conv_fp16_kernel<<<cgrid, 256, CONV_SMEM>>>(
        p_h1p, p_h1p + PSTR_W, p_h1p + 2 * (size_t)PSTR_W, p_w2p, c2b, p_h2, 0);
    ln_head_kernel<<<3 * 2048, 256>>>(p_h2, g2, b2, lw, lb, out + OFF_LOGDUR);
}

// round 9
// speedup vs baseline: 1.8930x; 1.0257x over previous
#include <cuda_runtime.h>
#include <cuda_fp16.h>
#include <cstdint>

#define B_  32
#define T_  512
#define H_  512
#define NB  256
#define MAXL 2048

// packed fp16 activation rows: 64 data halves (32 words) + pad -> 36 words
#define RW       36
#define APB_W    (514 * RW)          // words per (b,chunk);  8 chunks of 64ch
#define A_BSTR_W (8 * APB_W)         // words per b
#define PSTR_W   (32 * A_BSTR_W)     // words per predictor
// packed fp16 weights: [pred 3][nt 4][stage 24][n 128][RW]
#define WSLOT_W  (128 * RW)
#define WNT_W    (24 * WSLOT_W)
#define WP_W     (3 * 4 * WNT_W)

// ---------------- scratch ----------------
__device__ __align__(256) uint32_t g_xp [32 * A_BSTR_W];
__device__ __align__(256) uint32_t g_x2p[32 * A_BSTR_W];
__device__ __align__(256) uint32_t g_h1p[3 * PSTR_W];
__device__ __align__(256) uint32_t g_w1p[WP_W];
__device__ __align__(256) uint32_t g_w2p[WP_W];
__device__ __align__(256) uint32_t g_h2 [3 * B_ * T_ * 256];  // fp16 linear
__device__ float g_x3 [B_ * T_ * H_];
__device__ int   g_cum[B_ * T_];
__device__ int   g_ml [B_];

__device__ __forceinline__ uint32_t smem_u32(const void* p) {
    uint32_t a;
    asm("{ .reg .u64 t; cvta.to.shared.u64 t, %1; cvt.u32.u64 %0, t; }" : "=r"(a) : "l"(p));
    return a;
}
__device__ __forceinline__ uint32_t h2pack(float x, float y) {
    __half2 h = __floats2half2_rn(x, y);
    return *reinterpret_cast<uint32_t*>(&h);
}
__device__ __forceinline__ float2 h2unpack(uint32_t u) {
    __half2 h = *reinterpret_cast<__half2*>(&u);
    return __half22float2(h);
}

#define MBAR_INIT(a, n) \
    asm volatile("mbarrier.init.shared.b64 [%0], %1;" :: "r"(a), "r"(n) : "memory")
#define MBAR_EXPECT(a, bytes) \
    asm volatile("mbarrier.arrive.expect_tx.shared.b64 _, [%0], %1;" :: "r"(a), "r"(bytes) : "memory")
#define MBAR_WAIT(a, par) do {                                                   \
    uint32_t _m = (a); uint32_t _p = (par); uint32_t _d;                         \
    asm volatile("{ .reg .pred p;"                                               \
        " mbarrier.try_wait.parity.acquire.cta.shared::cta.b64 p, [%1], %2;"     \
        " selp.b32 %0, 1, 0, p; }" : "=r"(_d) : "r"(_m), "r"(_p) : "memory");    \
    if (!_d) {                                                                   \
        asm volatile("{ .reg .pred P1;"                                          \
            " WL_%=:"                                                            \
            " mbarrier.try_wait.parity.acquire.cta.shared::cta.b64 P1, [%0], %1, 0x989680;" \
            " @P1 bra.uni WD_%=;"                                                \
            " bra.uni WL_%=;"                                                    \
            " WD_%=: }" :: "r"(_m), "r"(_p) : "memory");                         \
    } } while (0)

__device__ __forceinline__ void bulk_ld(uint32_t dst, const void* src,
                                        uint32_t bytes, uint32_t mbar) {
    asm volatile(
        "cp.async.bulk.shared::cluster.global.mbarrier::complete_tx::bytes "
        "[%0], [%1], %2, [%3];"
        :: "r"(dst), "l"(src), "r"(bytes), "r"(mbar) : "memory");
}

// ---------------------------------------------------------------------------
// conv1d(K=3,pad=1) implicit GEMM, fp16 mma m16n8k16, 24-stage K=64 pipeline.
// CTA 128x128, 8 warps 4(M) x 2(N), warp tile 32x64, 2 CTAs/SM.
// smem: 64 mbar | A 2x18720 | B 4x18432 = 111232 B
// ---------------------------------------------------------------------------
#define A_BYTES (130 * RW * 4)     // 18720
#define B_BYTES (WSLOT_W * 4)      // 18432
#define SA_OFF  64
#define SB_OFF  (64 + 2 * A_BYTES)
#define CONV_SMEM (SB_OFF + 4 * B_BYTES)

extern __shared__ __align__(128) char csm[];

__global__ void __launch_bounds__(256, 2) conv_fp16_kernel(
    const uint32_t* __restrict__ in0, const uint32_t* __restrict__ in1,
    const uint32_t* __restrict__ in2, const uint32_t* __restrict__ wpk,
    const float* __restrict__ biasAll, uint32_t* __restrict__ outBase,
    int packedOut)
{
    const uint32_t sb = smem_u32(csm);
    const uint32_t* smw = (const uint32_t*)csm;
    const int tid  = threadIdx.x;
    const int lane = tid & 31, wid = tid >> 5;
    const int gr = lane >> 2, tc = lane & 3;
    const int wmm = wid & 3, wnn = wid >> 2;
    const int t0 = blockIdx.x * 128;
    const int n0 = blockIdx.y * 128;
    const int pred = blockIdx.z >> 5;
    const int b    = blockIdx.z & 31;

    const uint32_t* inP = (pred == 0) ? in0 : (pred == 1) ? in1 : in2;
    const uint32_t* aSrc = inP + (size_t)b * A_BSTR_W + (size_t)t0 * RW;
    const uint32_t* wB = wpk + (size_t)(pred * 4 + blockIdx.y) * WNT_W;
    const float* biasP = biasAll + pred * 512;

    if (tid == 0) {
#pragma unroll
        for (int i = 0; i < 6; i++) MBAR_INIT(sb + i * 8, 1);
    }
    __syncthreads();

#define ISSUE_A(c) do {                                                        \
    uint32_t mb = sb + ((c) & 1) * 8;                                          \
    MBAR_EXPECT(mb, A_BYTES);                                                  \
    bulk_ld(sb + SA_OFF + ((c) & 1) * A_BYTES, aSrc + (size_t)(c) * APB_W,     \
            A_BYTES, mb); } while (0)
#define ISSUE_B(s) do {                                                        \
    uint32_t mb = sb + 16 + ((s) & 3) * 8;                                     \
    MBAR_EXPECT(mb, B_BYTES);                                                  \
    bulk_ld(sb + SB_OFF + ((s) & 3) * B_BYTES, wB + (size_t)(s) * WSLOT_W,     \
            B_BYTES, mb); } while (0)

    if (tid == 0) { ISSUE_A(0); ISSUE_B(0); ISSUE_B(1); ISSUE_B(2); }

    float acc[2][8][4];
#pragma unroll
    for (int mi = 0; mi < 2; mi++)
#pragma unroll
        for (int ni = 0; ni < 8; ni++)
#pragma unroll
            for (int q = 0; q < 4; q++) acc[mi][ni][q] = 0.f;

    int c = 0, tap = 0;
    for (int s = 0; s < 24; ++s) {
        if (tid == 0) {
            if (tap == 0 && c + 1 < 8) ISSUE_A(c + 1);
            if (s + 3 < 24) ISSUE_B(s + 3);
        }
        MBAR_WAIT(sb + 16 + (s & 3) * 8, (s >> 2) & 1);
        if (tap == 0) MBAR_WAIT(sb + (c & 1) * 8, (c >> 1) & 1);

        const uint32_t* SA = smw + (SA_OFF >> 2) + (c & 1) * (A_BYTES >> 2)
                           + (wmm * 32 + tap + gr) * RW;
        const uint32_t* SB = smw + (SB_OFF >> 2) + (s & 3) * (B_BYTES >> 2)
                           + (wnn * 64 + gr) * RW;
#pragma unroll
        for (int ks = 0; ks < 4; ks++) {
            uint32_t a[2][4], bb[8][2];
#pragma unroll
            for (int mi = 0; mi < 2; mi++) {
                const uint32_t* Am = SA + mi * 16 * RW + ks * 8 + tc;
                a[mi][0] = Am[0];
                a[mi][1] = Am[8 * RW];
                a[mi][2] = Am[4];
                a[mi][3] = Am[8 * RW + 4];
            }
#pragma unroll
            for (int ni = 0; ni < 8; ni++) {
                const uint32_t* Bm = SB + ni * 8 * RW + ks * 8 + tc;
                bb[ni][0] = Bm[0];
                bb[ni][1] = Bm[4];
            }
#pragma unroll
            for (int mi = 0; mi < 2; mi++)
#pragma unroll
                for (int ni = 0; ni < 8; ni++)
                    asm volatile(
                        "mma.sync.aligned.m16n8k16.row.col.f32.f16.f16.f32 "
                        "{%0,%1,%2,%3}, {%4,%5,%6,%7}, {%8,%9}, {%0,%1,%2,%3};"
                        : "+f"(acc[mi][ni][0]), "+f"(acc[mi][ni][1]),
                          "+f"(acc[mi][ni][2]), "+f"(acc[mi][ni][3])
                        : "r"(a[mi][0]), "r"(a[mi][1]), "r"(a[mi][2]), "r"(a[mi][3]),
                          "r"(bb[ni][0]), "r"(bb[ni][1]));
        }
        __syncthreads();
        if (++tap == 3) { tap = 0; ++c; }
    }

    // epilogue: bias + ReLU, fp16 out
    const int r0 = t0 + wmm * 32 + gr;
    const int c0 = n0 + wnn * 64 + tc * 2;
    if (packedOut) {
        uint32_t* ob = outBase + (size_t)pred * PSTR_W + (size_t)b * A_BSTR_W;
#pragma unroll
        for (int ni = 0; ni < 8; ni++) {
            int col = c0 + ni * 8;
            int ch = col >> 6, wrd = (col & 63) >> 1;
            float b0 = __ldg(&biasP[col]), b1 = __ldg(&biasP[col + 1]);
            uint32_t* cb = ob + (size_t)ch * APB_W + wrd;
#pragma unroll
            for (int mi = 0; mi < 2; mi++) {
                int row = r0 + mi * 16;
                cb[(size_t)(row + 1) * RW] =
                    h2pack(fmaxf(acc[mi][ni][0] + b0, 0.f),
                           fmaxf(acc[mi][ni][1] + b1, 0.f));
                cb[(size_t)(row + 9) * RW] =
                    h2pack(fmaxf(acc[mi][ni][2] + b0, 0.f),
                           fmaxf(acc[mi][ni][3] + b1, 0.f));
            }
        }
    } else {
        uint32_t* ob = outBase + (size_t)pred * (B_ * T_ * 256)
                     + (size_t)b * (512 * 256);
#pragma unroll
        for (int ni = 0; ni < 8; ni++) {
            int col = c0 + ni * 8;
            float b0 = __ldg(&biasP[col]), b1 = __ldg(&biasP[col + 1]);
#pragma unroll
            for (int mi = 0; mi < 2; mi++) {
                int row = r0 + mi * 16;
                ob[(size_t)row * 256 + (col >> 1)] =
                    h2pack(fmaxf(acc[mi][ni][0] + b0, 0.f),
                           fmaxf(acc[mi][ni][1] + b1, 0.f));
                ob[(size_t)(row + 8) * 256 + (col >> 1)] =
                    h2pack(fmaxf(acc[mi][ni][2] + b0, 0.f),
                           fmaxf(acc[mi][ni][3] + b1, 0.f));
            }
        }
    }
}

// pack weights fp32 [pred][tap][cin][cout] -> fp16 [pred][nt][st 24][n 128][RW]
__global__ void __launch_bounds__(256) pack_w_kernel(
    const float* __restrict__ w, uint32_t* __restrict__ wp)
{
    int g = blockIdx.x * 256 + threadIdx.x;
    int wd = g % RW;
    int n  = (g / RW) % 128;
    int st = (g / WSLOT_W) % 24;
    int nt = (g / WNT_W) % 4;
    int pr = g / (4 * WNT_W);
    uint32_t o = 0;
    if (wd < 32) {
        int tap = st % 3, ch = st / 3, k = ch * 64 + 2 * wd;
        const float* s = w + ((size_t)((pr * 3 + tap) * 512 + k)) * 512
                       + nt * 128 + n;
        o = h2pack(s[0], s[512]);
    }
    wp[g] = o;
}

// fused prep: per token, bucketize pitch & energy targets;
//   xp  = fp16pack(x)                (packed layout)
//   x2p = fp16pack(x + ptab[pidx])   (packed layout)
//   x3  = x + ptab[pidx] + etab[eidx] (fp32 linear, for expand)
__global__ void __launch_bounds__(128) prep_x_kernel(
    const float* __restrict__ x,
    const float* __restrict__ pitch_t, const float* __restrict__ energy_t,
    const float* __restrict__ pbins, const float* __restrict__ ebins,
    const float* __restrict__ ptab, const float* __restrict__ etab,
    uint32_t* __restrict__ xp, uint32_t* __restrict__ x2p,
    float* __restrict__ x3)
{
    int token = blockIdx.x;
    int b = token >> 9, t = token & 511;
    float pv = pitch_t[token], ev = energy_t[token];
    int plo = 0, phi = NB - 1;
    while (plo < phi) { int m = (plo + phi) >> 1; if (pbins[m] < pv) plo = m + 1; else phi = m; }
    int elo = 0, ehi = NB - 1;
    while (elo < ehi) { int m = (elo + ehi) >> 1; if (ebins[m] < ev) elo = m + 1; else ehi = m; }

    int i = threadIdx.x;
    float4 a = ((const float4*)(x + (size_t)token * H_))[i];
    float4 p = ((const float4*)(ptab + (size_t)plo * H_))[i];
    float4 e = ((const float4*)(etab + (size_t)elo * H_))[i];
    float4 r2 = make_float4(a.x + p.x, a.y + p.y, a.z + p.z, a.w + p.w);
    ((float4*)(x3 + (size_t)token * H_))[i] =
        make_float4(r2.x + e.x, r2.y + e.y, r2.z + e.z, r2.w + e.w);

    int ch = i >> 4, w = (i & 15) * 2;
    size_t off = ((size_t)(b * 8 + ch) * 514 + t + 1) * RW + w;
    xp [off]     = h2pack(a.x,  a.y);
    xp [off + 1] = h2pack(a.z,  a.w);
    x2p[off]     = h2pack(r2.x, r2.y);
    x2p[off + 1] = h2pack(r2.z, r2.w);
}

// zero halo rows of xp (buf 0), x2p (buf 1), h1p (bufs 2..4)
__global__ void __launch_bounds__(256) zero_halo_kernel(
    uint32_t* __restrict__ xp, uint32_t* __restrict__ x2p,
    uint32_t* __restrict__ h1p)
{
    int g = blockIdx.x * 256 + threadIdx.x;           // 5*32*8*2*36 = 92160
    if (g >= 5 * 512 * RW) return;
    int wd = g % RW;
    int h  = (g / RW) & 1;
    int ch = (g / (2 * RW)) & 7;
    int b  = (g / (16 * RW)) & 31;
    int buf = g / (512 * RW);
    size_t idx = ((size_t)(b * 8 + ch) * 514 + (h ? 513 : 0)) * RW + wd;
    if (buf == 0)      xp[idx] = 0;
    else if (buf == 1) x2p[idx] = 0;
    else               h1p[(size_t)(buf - 2) * PSTR_W + idx] = 0;
}

// in-place LN on packed fp16 h1p. warp per token, 3 preds batched.
__global__ void __launch_bounds__(256) ln_packed_kernel(
    uint32_t* __restrict__ hp, const float* __restrict__ gAll,
    const float* __restrict__ btAll)
{
    int bid = blockIdx.x;
    int pred = bid >> 11;
    int tok = (bid & 2047) * 8 + (threadIdx.x >> 5);
    int lane = threadIdx.x & 31;
    int b = tok >> 9, t = tok & 511;
    uint32_t* base = hp + (size_t)pred * PSTR_W + (size_t)b * A_BSTR_W
                   + (size_t)(t + 1) * RW + lane;
    const float* g  = gAll + pred * 512;
    const float* bt = btAll + pred * 512;
    float2 v[8];
    float s = 0.f, s2 = 0.f;
#pragma unroll
    for (int j = 0; j < 8; j++) {
        v[j] = h2unpack(base[(size_t)j * APB_W]);
        s += v[j].x + v[j].y;
        s2 += v[j].x * v[j].x + v[j].y * v[j].y;
    }
#pragma unroll
    for (int o = 16; o; o >>= 1) {
        s  += __shfl_xor_sync(0xffffffffu, s,  o);
        s2 += __shfl_xor_sync(0xffffffffu, s2, o);
    }
    float mean = s * (1.f / 512.f);
    float var  = s2 * (1.f / 512.f) - mean * mean;
    float rs   = rsqrtf(var + 1e-5f);
#pragma unroll
    for (int j = 0; j < 8; j++) {
        int f = j * 64 + 2 * lane;
        base[(size_t)j * APB_W] =
            h2pack((v[j].x - mean) * rs * g[f] + bt[f],
                   (v[j].y - mean) * rs * g[f + 1] + bt[f + 1]);
    }
}

// LN + linear head on linear fp16 h2; 3 preds batched.
__global__ void __launch_bounds__(256) ln_head_kernel(
    const uint32_t* __restrict__ h2, const float* __restrict__ gAll,
    const float* __restrict__ btAll, const float* __restrict__ lwAll,
    const float* __restrict__ lb, float* __restrict__ outPred)
{
    int bid = blockIdx.x;
    int pred = bid >> 11;
    int token = (bid & 2047) * 8 + (threadIdx.x >> 5);
    int lane  = threadIdx.x & 31;
    const uint32_t* hr = h2 + (size_t)pred * (B_ * T_ * 256) + (size_t)token * 256;
    const float* g  = gAll + pred * 512;
    const float* bt = btAll + pred * 512;
    const float* lw = lwAll + pred * 512;
    float2 v[8];
    float s = 0.f, s2 = 0.f;
#pragma unroll
    for (int j = 0; j < 8; j++) {
        v[j] = h2unpack(hr[lane + 32 * j]);
        s += v[j].x + v[j].y;
        s2 += v[j].x * v[j].x + v[j].y * v[j].y;
    }
#pragma unroll
    for (int o = 16; o; o >>= 1) {
        s  += __shfl_xor_sync(0xffffffffu, s,  o);
        s2 += __shfl_xor_sync(0xffffffffu, s2, o);
    }
    float mean = s * (1.f / 512.f);
    float var  = s2 * (1.f / 512.f) - mean * mean;
    float rs   = rsqrtf(var + 1e-5f);
    float dot = 0.f;
#pragma unroll
    for (int j = 0; j < 8; j++) {
        int f = 2 * (lane + 32 * j);
        dot += ((v[j].x - mean) * rs * g[f] + bt[f]) * lw[f];
        dot += ((v[j].y - mean) * rs * g[f + 1] + bt[f + 1]) * lw[f + 1];
    }
#pragma unroll
    for (int o = 16; o; o >>= 1) dot += __shfl_xor_sync(0xffffffffu, dot, o);
    if (lane == 0) outPred[(size_t)pred * (B_ * T_) + token] = dot + lb[pred];
}

__global__ void __launch_bounds__(512) cumsum_kernel(
    const int* __restrict__ dur, int* __restrict__ cum,
    int* __restrict__ mellen, float* __restrict__ out_mellen)
{
    __shared__ int s[512];
    int b = blockIdx.x, t = threadIdx.x;
    s[t] = dur[b * T_ + t];
    __syncthreads();
    for (int off = 1; off < 512; off <<= 1) {
        int v = (t >= off) ? s[t - off] : 0;
        __syncthreads();
        s[t] += v;
        __syncthreads();
    }
    cum[b * T_ + t] = s[t];
    if (t == 511) {
        int ml = s[511] < MAXL ? s[511] : MAXL;
        mellen[b] = ml;
        out_mellen[b] = (float)ml;
    }
}

__global__ void __launch_bounds__(128) expand_kernel(
    const float* __restrict__ x3, const int* __restrict__ cum,
    const int* __restrict__ mellen, float* __restrict__ outx,
    float* __restrict__ outmask)
{
    int frame = blockIdx.x, b = blockIdx.y;
    int ml = mellen[b];
    float* orow = outx + ((size_t)b * MAXL + frame) * H_;
    bool masked = frame >= ml;
    if (threadIdx.x == 0) outmask[b * MAXL + frame] = masked ? 1.0f : 0.0f;
    if (masked) {
        ((float4*)orow)[threadIdx.x] = make_float4(0, 0, 0, 0);
        return;
    }
    const int* cb = cum + b * T_;
    int lo = 0, hi = T_;
    while (lo < hi) {
        int mid = (lo + hi) >> 1;
        if (cb[mid] <= frame) lo = mid + 1; else hi = mid;
    }
    if (lo > T_ - 1) lo = T_ - 1;
    ((float4*)orow)[threadIdx.x] =
        ((const float4*)(x3 + ((size_t)b * T_ + lo) * H_))[threadIdx.x];
}

extern "C" void kernel_launch(void* const* d_in, const int* in_sizes, int n_in,
                              void* d_out, int out_size)
{
    const float* x        = (const float*)d_in[0];
    const int*   duration = (const int*)  d_in[2];
    const float* pitch_t  = (const float*)d_in[3];
    const float* energy_t = (const float*)d_in[4];
    const float* c1w = (const float*)d_in[5];
    const float* c1b = (const float*)d_in[6];
    const float* g1  = (const float*)d_in[7];
    const float* b1  = (const float*)d_in[8];
    const float* c2w = (const float*)d_in[9];
    const float* c2b = (const float*)d_in[10];
    const float* g2  = (const float*)d_in[11];
    const float* b2  = (const float*)d_in[12];
    const float* lw  = (const float*)d_in[13];
    const float* lb  = (const float*)d_in[14];
    const float* pbins = (const float*)d_in[15];
    const float* ebins = (const float*)d_in[16];
    const float* ptab  = (const float*)d_in[17];
    const float* etab  = (const float*)d_in[18];

    float* out = (float*)d_out;
    const size_t OFF_LOGDUR = (size_t)B_ * MAXL * H_;
    const size_t OFF_MELLEN = OFF_LOGDUR + 3 * (size_t)B_ * T_;
    const size_t OFF_MASK   = OFF_MELLEN + B_;

    uint32_t *p_xp, *p_x2p, *p_h1p, *p_w1p, *p_w2p, *p_h2;
    float *p_x3;
    int *p_cum, *p_ml;
    cudaGetSymbolAddress((void**)&p_xp,  g_xp);
    cudaGetSymbolAddress((void**)&p_x2p, g_x2p);
    cudaGetSymbolAddress((void**)&p_h1p, g_h1p);
    cudaGetSymbolAddress((void**)&p_w1p, g_w1p);
    cudaGetSymbolAddress((void**)&p_w2p, g_w2p);
    cudaGetSymbolAddress((void**)&p_h2,  g_h2);
    cudaGetSymbolAddress((void**)&p_x3,  g_x3);
    cudaGetSymbolAddress((void**)&p_cum, g_cum);
    cudaGetSymbolAddress((void**)&p_ml,  g_ml);

    cudaFuncSetAttribute(conv_fp16_kernel,
                         cudaFuncAttributeMaxDynamicSharedMemorySize, CONV_SMEM);

    // ---- prep ----
    pack_w_kernel<<<WP_W / 256, 256>>>(c1w, p_w1p);
    pack_w_kernel<<<WP_W / 256, 256>>>(c2w, p_w2p);
    prep_x_kernel<<<B_ * T_, 128>>>(x, pitch_t, energy_t, pbins, ebins,
                                    ptab, etab, p_xp, p_x2p, p_x3);
    zero_halo_kernel<<<360, 256>>>(p_xp, p_x2p, p_h1p);

    // ---- LengthRegulator path ----
    cumsum_kernel<<<B_, 512>>>(duration, p_cum, p_ml, out + OFF_MELLEN);
    dim3 egrid(MAXL, B_);
    expand_kernel<<<egrid, 128>>>(p_x3, p_cum, p_ml, out, out + OFF_MASK);

    // ---- batched predictors ----
    dim3 cgrid(4, 4, 96);
    conv_fp16_kernel<<<cgrid, 256, CONV_SMEM>>>(
        p_xp, p_xp, p_x2p, p_w1p, c1b, p_h1p, 1);
    ln_packed_kernel<<<3 * 2048, 256>>>(p_h1p, g1, b1);
    conv_fp16_kernel<<<cgrid, 256, CONV_SMEM>>>(
        p_h1p, p_h1p + PSTR_W, p_h1p + 2 * (size_t)PSTR_W, p_w2p, c2b, p_h2, 0);
    ln_head_kernel<<<3 * 2048, 256>>>(p_h2, g2, b2, lw, lb, out + OFF_LOGDUR);
}

// round 10
// speedup vs baseline: 1.9295x; 1.0193x over previous
#include <cuda_runtime.h>
#include <cuda_fp16.h>
#include <cstdint>

#define B_  32
#define T_  512
#define H_  512
#define NB  256
#define MAXL 2048

// packed fp16 activation rows: 64 data halves (32 words) + pad -> 36 words
#define RW       36
#define APB_W    (514 * RW)
#define A_BSTR_W (8 * APB_W)
#define PSTR_W   (32 * A_BSTR_W)
// packed fp16 weights: [pred 3][nt 4][stage 24][n 128][RW]
#define WSLOT_W  (128 * RW)
#define WNT_W    (24 * WSLOT_W)
#define WP_W     (3 * 4 * WNT_W)

// ---------------- scratch ----------------
__device__ __align__(256) uint32_t g_xp [32 * A_BSTR_W];
__device__ __align__(256) uint32_t g_x2p[32 * A_BSTR_W];
__device__ __align__(256) uint32_t g_h1p[3 * PSTR_W];
__device__ __align__(256) uint32_t g_w1p[WP_W];
__device__ __align__(256) uint32_t g_w2p[WP_W];
__device__ __align__(256) uint32_t g_h2 [3 * B_ * T_ * 256];
__device__ float g_x3 [B_ * T_ * H_];
__device__ int   g_cum[B_ * T_];
__device__ int   g_ml [B_];

__device__ __forceinline__ uint32_t smem_u32(const void* p) {
    uint32_t a;
    asm("{ .reg .u64 t; cvta.to.shared.u64 t, %1; cvt.u32.u64 %0, t; }" : "=r"(a) : "l"(p));
    return a;
}
__device__ __forceinline__ uint32_t h2pack(float x, float y) {
    __half2 h = __floats2half2_rn(x, y);
    return *reinterpret_cast<uint32_t*>(&h);
}
__device__ __forceinline__ float2 h2unpack(uint32_t u) {
    __half2 h = *reinterpret_cast<__half2*>(&u);
    return __half22float2(h);
}

#define MBAR_INIT(a, n) \
    asm volatile("mbarrier.init.shared.b64 [%0], %1;" :: "r"(a), "r"(n) : "memory")
#define MBAR_EXPECT(a, bytes) \
    asm volatile("mbarrier.arrive.expect_tx.shared.b64 _, [%0], %1;" :: "r"(a), "r"(bytes) : "memory")
#define MBAR_WAIT(a, par) do {                                                   \
    uint32_t _m = (a); uint32_t _p = (par); uint32_t _d;                         \
    asm volatile("{ .reg .pred p;"                                               \
        " mbarrier.try_wait.parity.acquire.cta.shared::cta.b64 p, [%1], %2;"     \
        " selp.b32 %0, 1, 0, p; }" : "=r"(_d) : "r"(_m), "r"(_p) : "memory");    \
    if (!_d) {                                                                   \
        asm volatile("{ .reg .pred P1;"                                          \
            " WL_%=:"                                                            \
            " mbarrier.try_wait.parity.acquire.cta.shared::cta.b64 P1, [%0], %1, 0x989680;" \
            " @P1 bra.uni WD_%=;"                                                \
            " bra.uni WL_%=;"                                                    \
            " WD_%=: }" :: "r"(_m), "r"(_p) : "memory");                         \
    } } while (0)

__device__ __forceinline__ void bulk_ld(uint32_t dst, const void* src,
                                        uint32_t bytes, uint32_t mbar) {
    asm volatile(
        "cp.async.bulk.shared::cluster.global.mbarrier::complete_tx::bytes "
        "[%0], [%1], %2, [%3];"
        :: "r"(dst), "l"(src), "r"(bytes), "r"(mbar) : "memory");
}
#define LDSM_X4(r0, r1, r2, r3, addr) \
    asm volatile("ldmatrix.sync.aligned.m8n8.x4.shared.b16 {%0,%1,%2,%3}, [%4];" \
        : "=r"(r0), "=r"(r1), "=r"(r2), "=r"(r3) : "r"(addr))

// ---------------------------------------------------------------------------
// conv1d(K=3,pad=1) implicit GEMM, fp16 mma m16n8k16 + ldmatrix fragments.
// CTA 128x128, 8 warps 4(M) x 2(N), warp tile 32x64, 2 CTAs/SM.
// smem: 64 mbar | A 2x18720 | B 4x18432 = 111232 B
// ---------------------------------------------------------------------------
#define A_BYTES (130 * RW * 4)
#define B_BYTES (WSLOT_W * 4)
#define SA_OFF  64
#define SB_OFF  (64 + 2 * A_BYTES)
#define CONV_SMEM (SB_OFF + 4 * B_BYTES)

extern __shared__ __align__(128) char csm[];

__global__ void __launch_bounds__(256, 2) conv_fp16_kernel(
    const uint32_t* __restrict__ in0, const uint32_t* __restrict__ in1,
    const uint32_t* __restrict__ in2, const uint32_t* __restrict__ wpk,
    const float* __restrict__ biasAll, uint32_t* __restrict__ outBase,
    int packedOut)
{
    const uint32_t sb = smem_u32(csm);
    const int tid  = threadIdx.x;
    const int lane = tid & 31, wid = tid >> 5;
    const int gr = lane >> 2, tc = lane & 3;
    const int wmm = wid & 3, wnn = wid >> 2;
    const int t0 = blockIdx.x * 128;
    const int n0 = blockIdx.y * 128;
    const int pred = blockIdx.z >> 5;
    const int b    = blockIdx.z & 31;

    const uint32_t* inP = (pred == 0) ? in0 : (pred == 1) ? in1 : in2;
    const uint32_t* aSrc = inP + (size_t)b * A_BSTR_W + (size_t)t0 * RW;
    const uint32_t* wB = wpk + (size_t)(pred * 4 + blockIdx.y) * WNT_W;
    const float* biasP = biasAll + pred * 512;

    if (tid == 0) {
#pragma unroll
        for (int i = 0; i < 6; i++) MBAR_INIT(sb + i * 8, 1);
    }
    __syncthreads();

#define ISSUE_A(c) do {                                                        \
    uint32_t mb = sb + ((c) & 1) * 8;                                          \
    MBAR_EXPECT(mb, A_BYTES);                                                  \
    bulk_ld(sb + SA_OFF + ((c) & 1) * A_BYTES, aSrc + (size_t)(c) * APB_W,     \
            A_BYTES, mb); } while (0)
#define ISSUE_B(s) do {                                                        \
    uint32_t mb = sb + 16 + ((s) & 3) * 8;                                     \
    MBAR_EXPECT(mb, B_BYTES);                                                  \
    bulk_ld(sb + SB_OFF + ((s) & 3) * B_BYTES, wB + (size_t)(s) * WSLOT_W,     \
            B_BYTES, mb); } while (0)

    if (tid == 0) { ISSUE_A(0); ISSUE_B(0); ISSUE_B(1); ISSUE_B(2); }

    // ldmatrix lane geometry
    const int lm   = lane >> 3;                    // matrix index 0..3
    const int lrow = lane & 7;
    const int rA = lrow + (lm & 1) * 8;            // A row within 16
    const int kA = (lm >> 1) * 4;                  // A k-word within 8
    const int nB = (lm >> 1) * 8 + lrow;           // B col within 16
    const int kB = (lm & 1) * 4;                   // B k-word within 8

    float acc[2][8][4];
#pragma unroll
    for (int mi = 0; mi < 2; mi++)
#pragma unroll
        for (int ni = 0; ni < 8; ni++)
#pragma unroll
            for (int q = 0; q < 4; q++) acc[mi][ni][q] = 0.f;

    int c = 0, tap = 0;
    for (int s = 0; s < 24; ++s) {
        if (tid == 0) {
            if (tap == 0 && c + 1 < 8) ISSUE_A(c + 1);
            if (s + 3 < 24) ISSUE_B(s + 3);
        }
        MBAR_WAIT(sb + 16 + (s & 3) * 8, (s >> 2) & 1);
        if (tap == 0) MBAR_WAIT(sb + (c & 1) * 8, (c >> 1) & 1);

        const uint32_t aAddr0 = sb + SA_OFF + (c & 1) * A_BYTES
                              + ((wmm * 32 + tap + rA) * RW + kA) * 4;
        const uint32_t bAddr0 = sb + SB_OFF + (s & 3) * B_BYTES
                              + ((wnn * 64 + nB) * RW + kB) * 4;
#pragma unroll
        for (int ks = 0; ks < 4; ks++) {
            uint32_t a[2][4], bb[8][2];
#pragma unroll
            for (int mi = 0; mi < 2; mi++)
                LDSM_X4(a[mi][0], a[mi][1], a[mi][2], a[mi][3],
                        aAddr0 + (mi * 16 * RW + ks * 8) * 4);
#pragma unroll
            for (int p = 0; p < 4; p++)
                LDSM_X4(bb[2 * p][0], bb[2 * p][1], bb[2 * p + 1][0], bb[2 * p + 1][1],
                        bAddr0 + (p * 16 * RW + ks * 8) * 4);
#pragma unroll
            for (int mi = 0; mi < 2; mi++)
#pragma unroll
                for (int ni = 0; ni < 8; ni++)
                    asm volatile(
                        "mma.sync.aligned.m16n8k16.row.col.f32.f16.f16.f32 "
                        "{%0,%1,%2,%3}, {%4,%5,%6,%7}, {%8,%9}, {%0,%1,%2,%3};"
                        : "+f"(acc[mi][ni][0]), "+f"(acc[mi][ni][1]),
                          "+f"(acc[mi][ni][2]), "+f"(acc[mi][ni][3])
                        : "r"(a[mi][0]), "r"(a[mi][1]), "r"(a[mi][2]), "r"(a[mi][3]),
                          "r"(bb[ni][0]), "r"(bb[ni][1]));
        }
        __syncthreads();
        if (++tap == 3) { tap = 0; ++c; }
    }

    // epilogue: bias + ReLU, fp16 out
    const int r0 = t0 + wmm * 32 + gr;
    const int c0 = n0 + wnn * 64 + tc * 2;
    if (packedOut) {
        uint32_t* ob = outBase + (size_t)pred * PSTR_W + (size_t)b * A_BSTR_W;
#pragma unroll
        for (int ni = 0; ni < 8; ni++) {
            int col = c0 + ni * 8;
            int ch = col >> 6, wrd = (col & 63) >> 1;
            float b0 = __ldg(&biasP[col]), b1 = __ldg(&biasP[col + 1]);
            uint32_t* cb = ob + (size_t)ch * APB_W + wrd;
#pragma unroll
            for (int mi = 0; mi < 2; mi++) {
                int row = r0 + mi * 16;
                cb[(size_t)(row + 1) * RW] =
                    h2pack(fmaxf(acc[mi][ni][0] + b0, 0.f),
                           fmaxf(acc[mi][ni][1] + b1, 0.f));
                cb[(size_t)(row + 9) * RW] =
                    h2pack(fmaxf(acc[mi][ni][2] + b0, 0.f),
                           fmaxf(acc[mi][ni][3] + b1, 0.f));
            }
        }
    } else {
        uint32_t* ob = outBase + (size_t)pred * (B_ * T_ * 256)
                     + (size_t)b * (512 * 256);
#pragma unroll
        for (int ni = 0; ni < 8; ni++) {
            int col = c0 + ni * 8;
            float b0 = __ldg(&biasP[col]), b1 = __ldg(&biasP[col + 1]);
#pragma unroll
            for (int mi = 0; mi < 2; mi++) {
                int row = r0 + mi * 16;
                ob[(size_t)row * 256 + (col >> 1)] =
                    h2pack(fmaxf(acc[mi][ni][0] + b0, 0.f),
                           fmaxf(acc[mi][ni][1] + b1, 0.f));
                ob[(size_t)(row + 8) * 256 + (col >> 1)] =
                    h2pack(fmaxf(acc[mi][ni][2] + b0, 0.f),
                           fmaxf(acc[mi][ni][3] + b1, 0.f));
            }
        }
    }
}

// pack weights fp32 [pred][tap][cin][cout] -> fp16 [pred][nt][st 24][n 128][RW]
__global__ void __launch_bounds__(256) pack_w_kernel(
    const float* __restrict__ w, uint32_t* __restrict__ wp)
{
    int g = blockIdx.x * 256 + threadIdx.x;
    int wd = g % RW;
    int n  = (g / RW) % 128;
    int st = (g / WSLOT_W) % 24;
    int nt = (g / WNT_W) % 4;
    int pr = g / (4 * WNT_W);
    uint32_t o = 0;
    if (wd < 32) {
        int tap = st % 3, ch = st / 3, k = ch * 64 + 2 * wd;
        const float* s = w + ((size_t)((pr * 3 + tap) * 512 + k)) * 512
                       + nt * 128 + n;
        o = h2pack(s[0], s[512]);
    }
    wp[g] = o;
}

// fused prep: xp = fp16(x); x2p = fp16(x+pemb); x3 = x+pemb+eemb (fp32)
__global__ void __launch_bounds__(128) prep_x_kernel(
    const float* __restrict__ x,
    const float* __restrict__ pitch_t, const float* __restrict__ energy_t,
    const float* __restrict__ pbins, const float* __restrict__ ebins,
    const float* __restrict__ ptab, const float* __restrict__ etab,
    uint32_t* __restrict__ xp, uint32_t* __restrict__ x2p,
    float* __restrict__ x3)
{
    int token = blockIdx.x;
    int b = token >> 9, t = token & 511;
    float pv = pitch_t[token], ev = energy_t[token];
    int plo = 0, phi = NB - 1;
    while (plo < phi) { int m = (plo + phi) >> 1; if (pbins[m] < pv) plo = m + 1; else phi = m; }
    int elo = 0, ehi = NB - 1;
    while (elo < ehi) { int m = (elo + ehi) >> 1; if (ebins[m] < ev) elo = m + 1; else ehi = m; }

    int i = threadIdx.x;
    float4 a = ((const float4*)(x + (size_t)token * H_))[i];
    float4 p = ((const float4*)(ptab + (size_t)plo * H_))[i];
    float4 e = ((const float4*)(etab + (size_t)elo * H_))[i];
    float4 r2 = make_float4(a.x + p.x, a.y + p.y, a.z + p.z, a.w + p.w);
    ((float4*)(x3 + (size_t)token * H_))[i] =
        make_float4(r2.x + e.x, r2.y + e.y, r2.z + e.z, r2.w + e.w);

    int ch = i >> 4, w = (i & 15) * 2;
    size_t off = ((size_t)(b * 8 + ch) * 514 + t + 1) * RW + w;
    xp [off]     = h2pack(a.x,  a.y);
    xp [off + 1] = h2pack(a.z,  a.w);
    x2p[off]     = h2pack(r2.x, r2.y);
    x2p[off + 1] = h2pack(r2.z, r2.w);
}

// zero halo rows of xp (buf 0), x2p (buf 1), h1p (bufs 2..4)
__global__ void __launch_bounds__(256) zero_halo_kernel(
    uint32_t* __restrict__ xp, uint32_t* __restrict__ x2p,
    uint32_t* __restrict__ h1p)
{
    int g = blockIdx.x * 256 + threadIdx.x;
    if (g >= 5 * 512 * RW) return;
    int wd = g % RW;
    int h  = (g / RW) & 1;
    int ch = (g / (2 * RW)) & 7;
    int b  = (g / (16 * RW)) & 31;
    int buf = g / (512 * RW);
    size_t idx = ((size_t)(b * 8 + ch) * 514 + (h ? 513 : 0)) * RW + wd;
    if (buf == 0)      xp[idx] = 0;
    else if (buf == 1) x2p[idx] = 0;
    else               h1p[(size_t)(buf - 2) * PSTR_W + idx] = 0;
}

// in-place LN on packed fp16 h1p. warp per token, 3 preds batched.
__global__ void __launch_bounds__(256) ln_packed_kernel(
    uint32_t* __restrict__ hp, const float* __restrict__ gAll,
    const float* __restrict__ btAll)
{
    int bid = blockIdx.x;
    int pred = bid >> 11;
    int tok = (bid & 2047) * 8 + (threadIdx.x >> 5);
    int lane = threadIdx.x & 31;
    int b = tok >> 9, t = tok & 511;
    uint32_t* base = hp + (size_t)pred * PSTR_W + (size_t)b * A_BSTR_W
                   + (size_t)(t + 1) * RW + lane;
    const float* g  = gAll + pred * 512;
    const float* bt = btAll + pred * 512;
    float2 v[8];
    float s = 0.f, s2 = 0.f;
#pragma unroll
    for (int j = 0; j < 8; j++) {
        v[j] = h2unpack(base[(size_t)j * APB_W]);
        s += v[j].x + v[j].y;
        s2 += v[j].x * v[j].x + v[j].y * v[j].y;
    }
#pragma unroll
    for (int o = 16; o; o >>= 1) {
        s  += __shfl_xor_sync(0xffffffffu, s,  o);
        s2 += __shfl_xor_sync(0xffffffffu, s2, o);
    }
    float mean = s * (1.f / 512.f);
    float var  = s2 * (1.f / 512.f) - mean * mean;
    float rs   = rsqrtf(var + 1e-5f);
#pragma unroll
    for (int j = 0; j < 8; j++) {
        int f = j * 64 + 2 * lane;
        base[(size_t)j * APB_W] =
            h2pack((v[j].x - mean) * rs * g[f] + bt[f],
                   (v[j].y - mean) * rs * g[f + 1] + bt[f + 1]);
    }
}

// LN + linear head on linear fp16 h2; 3 preds batched.
__global__ void __launch_bounds__(256) ln_head_kernel(
    const uint32_t* __restrict__ h2, const float* __restrict__ gAll,
    const float* __restrict__ btAll, const float* __restrict__ lwAll,
    const float* __restrict__ lb, float* __restrict__ outPred)
{
    int bid = blockIdx.x;
    int pred = bid >> 11;
    int token = (bid & 2047) * 8 + (threadIdx.x >> 5);
    int lane  = threadIdx.x & 31;
    const uint32_t* hr = h2 + (size_t)pred * (B_ * T_ * 256) + (size_t)token * 256;
    const float* g  = gAll + pred * 512;
    const float* bt = btAll + pred * 512;
    const float* lw = lwAll + pred * 512;
    float2 v[8];
    float s = 0.f, s2 = 0.f;
#pragma unroll
    for (int j = 0; j < 8; j++) {
        v[j] = h2unpack(hr[lane + 32 * j]);
        s += v[j].x + v[j].y;
        s2 += v[j].x * v[j].x + v[j].y * v[j].y;
    }
#pragma unroll
    for (int o = 16; o; o >>= 1) {
        s  += __shfl_xor_sync(0xffffffffu, s,  o);
        s2 += __shfl_xor_sync(0xffffffffu, s2, o);
    }
    float mean = s * (1.f / 512.f);
    float var  = s2 * (1.f / 512.f) - mean * mean;
    float rs   = rsqrtf(var + 1e-5f);
    float dot = 0.f;
#pragma unroll
    for (int j = 0; j < 8; j++) {
        int f = 2 * (lane + 32 * j);
        dot += ((v[j].x - mean) * rs * g[f] + bt[f]) * lw[f];
        dot += ((v[j].y - mean) * rs * g[f + 1] + bt[f + 1]) * lw[f + 1];
    }
#pragma unroll
    for (int o = 16; o; o >>= 1) dot += __shfl_xor_sync(0xffffffffu, dot, o);
    if (lane == 0) outPred[(size_t)pred * (B_ * T_) + token] = dot + lb[pred];
}

__global__ void __launch_bounds__(512) cumsum_kernel(
    const int* __restrict__ dur, int* __restrict__ cum,
    int* __restrict__ mellen, float* __restrict__ out_mellen)
{
    __shared__ int s[512];
    int b = blockIdx.x, t = threadIdx.x;
    s[t] = dur[b * T_ + t];
    __syncthreads();
    for (int off = 1; off < 512; off <<= 1) {
        int v = (t >= off) ? s[t - off] : 0;
        __syncthreads();
        s[t] += v;
        __syncthreads();
    }
    cum[b * T_ + t] = s[t];
    if (t == 511) {
        int ml = s[511] < MAXL ? s[511] : MAXL;
        mellen[b] = ml;
        out_mellen[b] = (float)ml;
    }
}

__global__ void __launch_bounds__(128) expand_kernel(
    const float* __restrict__ x3, const int* __restrict__ cum,
    const int* __restrict__ mellen, float* __restrict__ outx,
    float* __restrict__ outmask)
{
    int frame = blockIdx.x, b = blockIdx.y;
    int ml = mellen[b];
    float* orow = outx + ((size_t)b * MAXL + frame) * H_;
    bool masked = frame >= ml;
    if (threadIdx.x == 0) outmask[b * MAXL + frame] = masked ? 1.0f : 0.0f;
    if (masked) {
        ((float4*)orow)[threadIdx.x] = make_float4(0, 0, 0, 0);
        return;
    }
    const int* cb = cum + b * T_;
    int lo = 0, hi = T_;
    while (lo < hi) {
        int mid = (lo + hi) >> 1;
        if (cb[mid] <= frame) lo = mid + 1; else hi = mid;
    }
    if (lo > T_ - 1) lo = T_ - 1;
    ((float4*)orow)[threadIdx.x] =
        ((const float4*)(x3 + ((size_t)b * T_ + lo) * H_))[threadIdx.x];
}

extern "C" void kernel_launch(void* const* d_in, const int* in_sizes, int n_in,
                              void* d_out, int out_size)
{
    const float* x        = (const float*)d_in[0];
    const int*   duration = (const int*)  d_in[2];
    const float* pitch_t  = (const float*)d_in[3];
    const float* energy_t = (const float*)d_in[4];
    const float* c1w = (const float*)d_in[5];
    const float* c1b = (const float*)d_in[6];
    const float* g1  = (const float*)d_in[7];
    const float* b1  = (const float*)d_in[8];
    const float* c2w = (const float*)d_in[9];
    const float* c2b = (const float*)d_in[10];
    const float* g2  = (const float*)d_in[11];
    const float* b2  = (const float*)d_in[12];
    const float* lw  = (const float*)d_in[13];
    const float* lb  = (const float*)d_in[14];
    const float* pbins = (const float*)d_in[15];
    const float* ebins = (const float*)d_in[16];
    const float* ptab  = (const float*)d_in[17];
    const float* etab  = (const float*)d_in[18];

    float* out = (float*)d_out;
    const size_t OFF_LOGDUR = (size_t)B_ * MAXL * H_;
    const size_t OFF_MELLEN = OFF_LOGDUR + 3 * (size_t)B_ * T_;
    const size_t OFF_MASK   = OFF_MELLEN + B_;

    uint32_t *p_xp, *p_x2p, *p_h1p, *p_w1p, *p_w2p, *p_h2;
    float *p_x3;
    int *p_cum, *p_ml;
    cudaGetSymbolAddress((void**)&p_xp,  g_xp);
    cudaGetSymbolAddress((void**)&p_x2p, g_x2p);
    cudaGetSymbolAddress((void**)&p_h1p, g_h1p);
    cudaGetSymbolAddress((void**)&p_w1p, g_w1p);
    cudaGetSymbolAddress((void**)&p_w2p, g_w2p);
    cudaGetSymbolAddress((void**)&p_h2,  g_h2);
    cudaGetSymbolAddress((void**)&p_x3,  g_x3);
    cudaGetSymbolAddress((void**)&p_cum, g_cum);
    cudaGetSymbolAddress((void**)&p_ml,  g_ml);

    cudaFuncSetAttribute(conv_fp16_kernel,
                         cudaFuncAttributeMaxDynamicSharedMemorySize, CONV_SMEM);

    // ---- prep ----
    pack_w_kernel<<<WP_W / 256, 256>>>(c1w, p_w1p);
    pack_w_kernel<<<WP_W / 256, 256>>>(c2w, p_w2p);
    prep_x_kernel<<<B_ * T_, 128>>>(x, pitch_t, energy_t, pbins, ebins,
                                    ptab, etab, p_xp, p_x2p, p_x3);
    zero_halo_kernel<<<360, 256>>>(p_xp, p_x2p, p_h1p);

    // ---- LengthRegulator path ----
    cumsum_kernel<<<B_, 512>>>(duration, p_cum, p_ml, out + OFF_MELLEN);
    dim3 egrid(MAXL, B_);
    expand_kernel<<<egrid, 128>>>(p_x3, p_cum, p_ml, out, out + OFF_MASK);

    // ---- batched predictors ----
    dim3 cgrid(4, 4, 96);
    conv_fp16_kernel<<<cgrid, 256, CONV_SMEM>>>(
        p_xp, p_xp, p_x2p, p_w1p, c1b, p_h1p, 1);
    ln_packed_kernel<<<3 * 2048, 256>>>(p_h1p, g1, b1);
    conv_fp16_kernel<<<cgrid, 256, CONV_SMEM>>>(
        p_h1p, p_h1p + PSTR_W, p_h1p + 2 * (size_t)PSTR_W, p_w2p, c2b, p_h2, 0);
    ln_head_kernel<<<3 * 2048, 256>>>(p_h2, g2, b2, lw, lb, out + OFF_LOGDUR);
}

// round 11
// speedup vs baseline: 1.9705x; 1.0213x over previous
#include <cuda_runtime.h>
#include <cuda_fp16.h>
#include <cstdint>

#define B_  32
#define T_  512
#define H_  512
#define NB  256
#define MAXL 2048

// packed fp16 activation rows: 64 data halves (32 words) + pad -> 36 words
#define RW       36
#define APB_W    (514 * RW)
#define A_BSTR_W (8 * APB_W)
#define PSTR_W   (32 * A_BSTR_W)
// packed fp16 weights: [pred 3][nt 4][stage 24][n 128][RW]
#define WSLOT_W  (128 * RW)
#define WNT_W    (24 * WSLOT_W)
#define WP_W     (3 * 4 * WNT_W)

// ---------------- scratch ----------------
__device__ __align__(256) uint32_t g_xp [32 * A_BSTR_W];
__device__ __align__(256) uint32_t g_x2p[32 * A_BSTR_W];
__device__ __align__(256) uint32_t g_h1p[3 * PSTR_W];
__device__ __align__(256) uint32_t g_w1p[WP_W];
__device__ __align__(256) uint32_t g_w2p[WP_W];
__device__ __align__(256) uint32_t g_h2 [3 * B_ * T_ * 256];
__device__ float g_x3 [B_ * T_ * H_];
__device__ int   g_cum[B_ * T_];
__device__ int   g_ml [B_];

__device__ __forceinline__ uint32_t smem_u32(const void* p) {
    uint32_t a;
    asm("{ .reg .u64 t; cvta.to.shared.u64 t, %1; cvt.u32.u64 %0, t; }" : "=r"(a) : "l"(p));
    return a;
}
__device__ __forceinline__ uint32_t h2pack(float x, float y) {
    __half2 h = __floats2half2_rn(x, y);
    return *reinterpret_cast<uint32_t*>(&h);
}
__device__ __forceinline__ float2 h2unpack(uint32_t u) {
    __half2 h = *reinterpret_cast<__half2*>(&u);
    return __half22float2(h);
}

#define MBAR_INIT(a, n) \
    asm volatile("mbarrier.init.shared.b64 [%0], %1;" :: "r"(a), "r"(n) : "memory")
#define MBAR_EXPECT(a, bytes) \
    asm volatile("mbarrier.arrive.expect_tx.shared.b64 _, [%0], %1;" :: "r"(a), "r"(bytes) : "memory")
#define MBAR_WAIT(a, par) do {                                                   \
    uint32_t _m = (a); uint32_t _p = (par); uint32_t _d;                         \
    asm volatile("{ .reg .pred p;"                                               \
        " mbarrier.try_wait.parity.acquire.cta.shared::cta.b64 p, [%1], %2;"     \
        " selp.b32 %0, 1, 0, p; }" : "=r"(_d) : "r"(_m), "r"(_p) : "memory");    \
    if (!_d) {                                                                   \
        asm volatile("{ .reg .pred P1;"                                          \
            " WL_%=:"                                                            \
            " mbarrier.try_wait.parity.acquire.cta.shared::cta.b64 P1, [%0], %1, 0x989680;" \
            " @P1 bra.uni WD_%=;"                                                \
            " bra.uni WL_%=;"                                                    \
            " WD_%=: }" :: "r"(_m), "r"(_p) : "memory");                         \
    } } while (0)

__device__ __forceinline__ void bulk_ld(uint32_t dst, const void* src,
                                        uint32_t bytes, uint32_t mbar) {
    asm volatile(
        "cp.async.bulk.shared::cluster.global.mbarrier::complete_tx::bytes "
        "[%0], [%1], %2, [%3];"
        :: "r"(dst), "l"(src), "r"(bytes), "r"(mbar) : "memory");
}
#define LDSM_X4(r0, r1, r2, r3, addr) \
    asm volatile("ldmatrix.sync.aligned.m8n8.x4.shared.b16 {%0,%1,%2,%3}, [%4];" \
        : "=r"(r0), "=r"(r1), "=r"(r2), "=r"(r3) : "r"(addr))

// ---------------------------------------------------------------------------
// conv1d(K=3,pad=1) implicit GEMM, fp16 mma m16n8k16 + ldmatrix fragments.
// CTA 128x128, 8 warps 4(M) x 2(N), warp tile 32x64, 2 CTAs/SM.
// ---------------------------------------------------------------------------
#define A_BYTES (130 * RW * 4)
#define B_BYTES (WSLOT_W * 4)
#define SA_OFF  64
#define SB_OFF  (64 + 2 * A_BYTES)
#define CONV_SMEM (SB_OFF + 4 * B_BYTES)

extern __shared__ __align__(128) char csm[];

__global__ void __launch_bounds__(256, 2) conv_fp16_kernel(
    const uint32_t* __restrict__ in0, const uint32_t* __restrict__ in1,
    const uint32_t* __restrict__ in2, const uint32_t* __restrict__ wpk,
    const float* __restrict__ biasAll, uint32_t* __restrict__ outBase,
    int packedOut)
{
    const uint32_t sb = smem_u32(csm);
    const int tid  = threadIdx.x;
    const int lane = tid & 31, wid = tid >> 5;
    const int gr = lane >> 2, tc = lane & 3;
    const int wmm = wid & 3, wnn = wid >> 2;
    const int t0 = blockIdx.x * 128;
    const int n0 = blockIdx.y * 128;
    const int pred = blockIdx.z >> 5;
    const int b    = blockIdx.z & 31;

    const uint32_t* inP = (pred == 0) ? in0 : (pred == 1) ? in1 : in2;
    const uint32_t* aSrc = inP + (size_t)b * A_BSTR_W + (size_t)t0 * RW;
    const uint32_t* wB = wpk + (size_t)(pred * 4 + blockIdx.y) * WNT_W;
    const float* biasP = biasAll + pred * 512;

    if (tid == 0) {
#pragma unroll
        for (int i = 0; i < 6; i++) MBAR_INIT(sb + i * 8, 1);
    }
    __syncthreads();

#define ISSUE_A(c) do {                                                        \
    uint32_t mb = sb + ((c) & 1) * 8;                                          \
    MBAR_EXPECT(mb, A_BYTES);                                                  \
    bulk_ld(sb + SA_OFF + ((c) & 1) * A_BYTES, aSrc + (size_t)(c) * APB_W,     \
            A_BYTES, mb); } while (0)
#define ISSUE_B(s) do {                                                        \
    uint32_t mb = sb + 16 + ((s) & 3) * 8;                                     \
    MBAR_EXPECT(mb, B_BYTES);                                                  \
    bulk_ld(sb + SB_OFF + ((s) & 3) * B_BYTES, wB + (size_t)(s) * WSLOT_W,     \
            B_BYTES, mb); } while (0)

    if (tid == 0) { ISSUE_A(0); ISSUE_B(0); ISSUE_B(1); ISSUE_B(2); }

    // ldmatrix lane geometry
    const int lm   = lane >> 3;
    const int lrow = lane & 7;
    const int rA = lrow + (lm & 1) * 8;
    const int kA = (lm >> 1) * 4;
    const int nB = (lm >> 1) * 8 + lrow;
    const int kB = (lm & 1) * 4;

    float acc[2][8][4];
#pragma unroll
    for (int mi = 0; mi < 2; mi++)
#pragma unroll
        for (int ni = 0; ni < 8; ni++)
#pragma unroll
            for (int q = 0; q < 4; q++) acc[mi][ni][q] = 0.f;

    int c = 0, tap = 0;
    for (int s = 0; s < 24; ++s) {
        if (tid == 0) {
            if (tap == 0 && c + 1 < 8) ISSUE_A(c + 1);
            if (s + 3 < 24) ISSUE_B(s + 3);
        }
        MBAR_WAIT(sb + 16 + (s & 3) * 8, (s >> 2) & 1);
        if (tap == 0) MBAR_WAIT(sb + (c & 1) * 8, (c >> 1) & 1);

        const uint32_t aAddr0 = sb + SA_OFF + (c & 1) * A_BYTES
                              + ((wmm * 32 + tap + rA) * RW + kA) * 4;
        const uint32_t bAddr0 = sb + SB_OFF + (s & 3) * B_BYTES
                              + ((wnn * 64 + nB) * RW + kB) * 4;
#pragma unroll
        for (int ks = 0; ks < 4; ks++) {
            uint32_t a[2][4], bb[8][2];
#pragma unroll
            for (int mi = 0; mi < 2; mi++)
                LDSM_X4(a[mi][0], a[mi][1], a[mi][2], a[mi][3],
                        aAddr0 + (mi * 16 * RW + ks * 8) * 4);
#pragma unroll
            for (int p = 0; p < 4; p++)
                LDSM_X4(bb[2 * p][0], bb[2 * p][1], bb[2 * p + 1][0], bb[2 * p + 1][1],
                        bAddr0 + (p * 16 * RW + ks * 8) * 4);
#pragma unroll
            for (int mi = 0; mi < 2; mi++)
#pragma unroll
                for (int ni = 0; ni < 8; ni++)
                    asm volatile(
                        "mma.sync.aligned.m16n8k16.row.col.f32.f16.f16.f32 "
                        "{%0,%1,%2,%3}, {%4,%5,%6,%7}, {%8,%9}, {%0,%1,%2,%3};"
                        : "+f"(acc[mi][ni][0]), "+f"(acc[mi][ni][1]),
                          "+f"(acc[mi][ni][2]), "+f"(acc[mi][ni][3])
                        : "r"(a[mi][0]), "r"(a[mi][1]), "r"(a[mi][2]), "r"(a[mi][3]),
                          "r"(bb[ni][0]), "r"(bb[ni][1]));
        }
        __syncthreads();
        if (++tap == 3) { tap = 0; ++c; }
    }

    // epilogue: bias + ReLU, fp16 out
    const int r0 = t0 + wmm * 32 + gr;
    const int c0 = n0 + wnn * 64 + tc * 2;
    if (packedOut) {
        uint32_t* ob = outBase + (size_t)pred * PSTR_W + (size_t)b * A_BSTR_W;
#pragma unroll
        for (int ni = 0; ni < 8; ni++) {
            int col = c0 + ni * 8;
            int ch = col >> 6, wrd = (col & 63) >> 1;
            float b0 = __ldg(&biasP[col]), b1 = __ldg(&biasP[col + 1]);
            uint32_t* cb = ob + (size_t)ch * APB_W + wrd;
#pragma unroll
            for (int mi = 0; mi < 2; mi++) {
                int row = r0 + mi * 16;
                cb[(size_t)(row + 1) * RW] =
                    h2pack(fmaxf(acc[mi][ni][0] + b0, 0.f),
                           fmaxf(acc[mi][ni][1] + b1, 0.f));
                cb[(size_t)(row + 9) * RW] =
                    h2pack(fmaxf(acc[mi][ni][2] + b0, 0.f),
                           fmaxf(acc[mi][ni][3] + b1, 0.f));
            }
        }
    } else {
        uint32_t* ob = outBase + (size_t)pred * (B_ * T_ * 256)
                     + (size_t)b * (512 * 256);
#pragma unroll
        for (int ni = 0; ni < 8; ni++) {
            int col = c0 + ni * 8;
            float b0 = __ldg(&biasP[col]), b1 = __ldg(&biasP[col + 1]);
#pragma unroll
            for (int mi = 0; mi < 2; mi++) {
                int row = r0 + mi * 16;
                ob[(size_t)row * 256 + (col >> 1)] =
                    h2pack(fmaxf(acc[mi][ni][0] + b0, 0.f),
                           fmaxf(acc[mi][ni][1] + b1, 0.f));
                ob[(size_t)(row + 8) * 256 + (col >> 1)] =
                    h2pack(fmaxf(acc[mi][ni][2] + b0, 0.f),
                           fmaxf(acc[mi][ni][3] + b1, 0.f));
            }
        }
    }
}

// pack weights fp32 [pred][tap][cin][cout] -> fp16 [pred][nt][st 24][n 128][RW]
__global__ void __launch_bounds__(256) pack_w_kernel(
    const float* __restrict__ w, uint32_t* __restrict__ wp)
{
    int g = blockIdx.x * 256 + threadIdx.x;
    int wd = g % RW;
    int n  = (g / RW) % 128;
    int st = (g / WSLOT_W) % 24;
    int nt = (g / WNT_W) % 4;
    int pr = g / (4 * WNT_W);
    uint32_t o = 0;
    if (wd < 32) {
        int tap = st % 3, ch = st / 3, k = ch * 64 + 2 * wd;
        const float* s = w + ((size_t)((pr * 3 + tap) * 512 + k)) * 512
                       + nt * 128 + n;
        o = h2pack(s[0], s[512]);
    }
    wp[g] = o;
}

// fused prep: xp = fp16(x); x2p = fp16(x+pemb); x3 = x+pemb+eemb (fp32)
__global__ void __launch_bounds__(128) prep_x_kernel(
    const float* __restrict__ x,
    const float* __restrict__ pitch_t, const float* __restrict__ energy_t,
    const float* __restrict__ pbins, const float* __restrict__ ebins,
    const float* __restrict__ ptab, const float* __restrict__ etab,
    uint32_t* __restrict__ xp, uint32_t* __restrict__ x2p,
    float* __restrict__ x3)
{
    int token = blockIdx.x;
    int b = token >> 9, t = token & 511;
    float pv = pitch_t[token], ev = energy_t[token];
    int plo = 0, phi = NB - 1;
    while (plo < phi) { int m = (plo + phi) >> 1; if (pbins[m] < pv) plo = m + 1; else phi = m; }
    int elo = 0, ehi = NB - 1;
    while (elo < ehi) { int m = (elo + ehi) >> 1; if (ebins[m] < ev) elo = m + 1; else ehi = m; }

    int i = threadIdx.x;
    float4 a = ((const float4*)(x + (size_t)token * H_))[i];
    float4 p = ((const float4*)(ptab + (size_t)plo * H_))[i];
    float4 e = ((const float4*)(etab + (size_t)elo * H_))[i];
    float4 r2 = make_float4(a.x + p.x, a.y + p.y, a.z + p.z, a.w + p.w);
    ((float4*)(x3 + (size_t)token * H_))[i] =
        make_float4(r2.x + e.x, r2.y + e.y, r2.z + e.z, r2.w + e.w);

    int ch = i >> 4, w = (i & 15) * 2;
    size_t off = ((size_t)(b * 8 + ch) * 514 + t + 1) * RW + w;
    xp [off]     = h2pack(a.x,  a.y);
    xp [off + 1] = h2pack(a.z,  a.w);
    x2p[off]     = h2pack(r2.x, r2.y);
    x2p[off + 1] = h2pack(r2.z, r2.w);
}

// zero halo rows of xp (buf 0), x2p (buf 1), h1p (bufs 2..4)
__global__ void __launch_bounds__(256) zero_halo_kernel(
    uint32_t* __restrict__ xp, uint32_t* __restrict__ x2p,
    uint32_t* __restrict__ h1p)
{
    int g = blockIdx.x * 256 + threadIdx.x;
    if (g >= 5 * 512 * RW) return;
    int wd = g % RW;
    int h  = (g / RW) & 1;
    int ch = (g / (2 * RW)) & 7;
    int b  = (g / (16 * RW)) & 31;
    int buf = g / (512 * RW);
    size_t idx = ((size_t)(b * 8 + ch) * 514 + (h ? 513 : 0)) * RW + wd;
    if (buf == 0)      xp[idx] = 0;
    else if (buf == 1) x2p[idx] = 0;
    else               h1p[(size_t)(buf - 2) * PSTR_W + idx] = 0;
}

// in-place LN on packed fp16 h1p. warp per token, 3 preds batched.
__global__ void __launch_bounds__(256) ln_packed_kernel(
    uint32_t* __restrict__ hp, const float* __restrict__ gAll,
    const float* __restrict__ btAll)
{
    int bid = blockIdx.x;
    int pred = bid >> 11;
    int tok = (bid & 2047) * 8 + (threadIdx.x >> 5);
    int lane = threadIdx.x & 31;
    int b = tok >> 9, t = tok & 511;
    uint32_t* base = hp + (size_t)pred * PSTR_W + (size_t)b * A_BSTR_W
                   + (size_t)(t + 1) * RW + lane;
    const float* g  = gAll + pred * 512;
    const float* bt = btAll + pred * 512;
    float2 v[8];
    float s = 0.f, s2 = 0.f;
#pragma unroll
    for (int j = 0; j < 8; j++) {
        v[j] = h2unpack(base[(size_t)j * APB_W]);
        s += v[j].x + v[j].y;
        s2 += v[j].x * v[j].x + v[j].y * v[j].y;
    }
#pragma unroll
    for (int o = 16; o; o >>= 1) {
        s  += __shfl_xor_sync(0xffffffffu, s,  o);
        s2 += __shfl_xor_sync(0xffffffffu, s2, o);
    }
    float mean = s * (1.f / 512.f);
    float var  = s2 * (1.f / 512.f) - mean * mean;
    float rs   = rsqrtf(var + 1e-5f);
#pragma unroll
    for (int j = 0; j < 8; j++) {
        int f = j * 64 + 2 * lane;
        base[(size_t)j * APB_W] =
            h2pack((v[j].x - mean) * rs * g[f] + bt[f],
                   (v[j].y - mean) * rs * g[f + 1] + bt[f + 1]);
    }
}

// LN + linear head on linear fp16 h2; 3 preds batched.
__global__ void __launch_bounds__(256) ln_head_kernel(
    const uint32_t* __restrict__ h2, const float* __restrict__ gAll,
    const float* __restrict__ btAll, const float* __restrict__ lwAll,
    const float* __restrict__ lb, float* __restrict__ outPred)
{
    int bid = blockIdx.x;
    int pred = bid >> 11;
    int token = (bid & 2047) * 8 + (threadIdx.x >> 5);
    int lane  = threadIdx.x & 31;
    const uint32_t* hr = h2 + (size_t)pred * (B_ * T_ * 256) + (size_t)token * 256;
    const float* g  = gAll + pred * 512;
    const float* bt = btAll + pred * 512;
    const float* lw = lwAll + pred * 512;
    float2 v[8];
    float s = 0.f, s2 = 0.f;
#pragma unroll
    for (int j = 0; j < 8; j++) {
        v[j] = h2unpack(hr[lane + 32 * j]);
        s += v[j].x + v[j].y;
        s2 += v[j].x * v[j].x + v[j].y * v[j].y;
    }
#pragma unroll
    for (int o = 16; o; o >>= 1) {
        s  += __shfl_xor_sync(0xffffffffu, s,  o);
        s2 += __shfl_xor_sync(0xffffffffu, s2, o);
    }
    float mean = s * (1.f / 512.f);
    float var  = s2 * (1.f / 512.f) - mean * mean;
    float rs   = rsqrtf(var + 1e-5f);
    float dot = 0.f;
#pragma unroll
    for (int j = 0; j < 8; j++) {
        int f = 2 * (lane + 32 * j);
        dot += ((v[j].x - mean) * rs * g[f] + bt[f]) * lw[f];
        dot += ((v[j].y - mean) * rs * g[f + 1] + bt[f + 1]) * lw[f + 1];
    }
#pragma unroll
    for (int o = 16; o; o >>= 1) dot += __shfl_xor_sync(0xffffffffu, dot, o);
    if (lane == 0) outPred[(size_t)pred * (B_ * T_) + token] = dot + lb[pred];
}

__global__ void __launch_bounds__(512) cumsum_kernel(
    const int* __restrict__ dur, int* __restrict__ cum,
    int* __restrict__ mellen, float* __restrict__ out_mellen)
{
    __shared__ int s[512];
    int b = blockIdx.x, t = threadIdx.x;
    s[t] = dur[b * T_ + t];
    __syncthreads();
    for (int off = 1; off < 512; off <<= 1) {
        int v = (t >= off) ? s[t - off] : 0;
        __syncthreads();
        s[t] += v;
        __syncthreads();
    }
    cum[b * T_ + t] = s[t];
    if (t == 511) {
        int ml = s[511] < MAXL ? s[511] : MAXL;
        mellen[b] = ml;
        out_mellen[b] = (float)ml;
    }
}

__global__ void __launch_bounds__(128) expand_kernel(
    const float* __restrict__ x3, const int* __restrict__ cum,
    const int* __restrict__ mellen, float* __restrict__ outx,
    float* __restrict__ outmask)
{
    int frame = blockIdx.x, b = blockIdx.y;
    int ml = mellen[b];
    float* orow = outx + ((size_t)b * MAXL + frame) * H_;
    bool masked = frame >= ml;
    if (threadIdx.x == 0) outmask[b * MAXL + frame] = masked ? 1.0f : 0.0f;
    if (masked) {
        ((float4*)orow)[threadIdx.x] = make_float4(0, 0, 0, 0);
        return;
    }
    const int* cb = cum + b * T_;
    int lo = 0, hi = T_;
    while (lo < hi) {
        int mid = (lo + hi) >> 1;
        if (cb[mid] <= frame) lo = mid + 1; else hi = mid;
    }
    if (lo > T_ - 1) lo = T_ - 1;
    ((float4*)orow)[threadIdx.x] =
        ((const float4*)(x3 + ((size_t)b * T_ + lo) * H_))[threadIdx.x];
}

extern "C" void kernel_launch(void* const* d_in, const int* in_sizes, int n_in,
                              void* d_out, int out_size)
{
    const float* x        = (const float*)d_in[0];
    const int*   duration = (const int*)  d_in[2];
    const float* pitch_t  = (const float*)d_in[3];
    const float* energy_t = (const float*)d_in[4];
    const float* c1w = (const float*)d_in[5];
    const float* c1b = (const float*)d_in[6];
    const float* g1  = (const float*)d_in[7];
    const float* b1  = (const float*)d_in[8];
    const float* c2w = (const float*)d_in[9];
    const float* c2b = (const float*)d_in[10];
    const float* g2  = (const float*)d_in[11];
    const float* b2  = (const float*)d_in[12];
    const float* lw  = (const float*)d_in[13];
    const float* lb  = (const float*)d_in[14];
    const float* pbins = (const float*)d_in[15];
    const float* ebins = (const float*)d_in[16];
    const float* ptab  = (const float*)d_in[17];
    const float* etab  = (const float*)d_in[18];

    float* out = (float*)d_out;
    const size_t OFF_LOGDUR = (size_t)B_ * MAXL * H_;
    const size_t OFF_MELLEN = OFF_LOGDUR + 3 * (size_t)B_ * T_;
    const size_t OFF_MASK   = OFF_MELLEN + B_;

    uint32_t *p_xp, *p_x2p, *p_h1p, *p_w1p, *p_w2p, *p_h2;
    float *p_x3;
    int *p_cum, *p_ml;
    cudaGetSymbolAddress((void**)&p_xp,  g_xp);
    cudaGetSymbolAddress((void**)&p_x2p, g_x2p);
    cudaGetSymbolAddress((void**)&p_h1p, g_h1p);
    cudaGetSymbolAddress((void**)&p_w1p, g_w1p);
    cudaGetSymbolAddress((void**)&p_w2p, g_w2p);
    cudaGetSymbolAddress((void**)&p_h2,  g_h2);
    cudaGetSymbolAddress((void**)&p_x3,  g_x3);
    cudaGetSymbolAddress((void**)&p_cum, g_cum);
    cudaGetSymbolAddress((void**)&p_ml,  g_ml);

    cudaFuncSetAttribute(conv_fp16_kernel,
                         cudaFuncAttributeMaxDynamicSharedMemorySize, CONV_SMEM);

    // side stream + events for graph-level fork (created per call; cheap,
    // and graph replay carries only the dependency structure)
    cudaStream_t side;
    cudaStreamCreateWithFlags(&side, cudaStreamNonBlocking);
    cudaEvent_t evFork, evJoin;
    cudaEventCreateWithFlags(&evFork, cudaEventDisableTiming);
    cudaEventCreateWithFlags(&evJoin, cudaEventDisableTiming);

    // ---- prep (main stream) ----
    pack_w_kernel<<<WP_W / 256, 256>>>(c1w, p_w1p);
    pack_w_kernel<<<WP_W / 256, 256>>>(c2w, p_w2p);
    prep_x_kernel<<<B_ * T_, 128>>>(x, pitch_t, energy_t, pbins, ebins,
                                    ptab, etab, p_xp, p_x2p, p_x3);
    zero_halo_kernel<<<360, 256>>>(p_xp, p_x2p, p_h1p);

    // fork: LengthRegulator branch runs concurrently with the conv chain
    cudaEventRecord(evFork, 0);
    cudaStreamWaitEvent(side, evFork, 0);
    cumsum_kernel<<<B_, 512, 0, side>>>(duration, p_cum, p_ml, out + OFF_MELLEN);
    dim3 egrid(MAXL, B_);
    expand_kernel<<<egrid, 128, 0, side>>>(p_x3, p_cum, p_ml, out, out + OFF_MASK);
    cudaEventRecord(evJoin, side);

    // ---- batched predictors (main stream) ----
    dim3 cgrid(4, 4, 96);
    conv_fp16_kernel<<<cgrid, 256, CONV_SMEM>>>(
        p_xp, p_xp, p_x2p, p_w1p, c1b, p_h1p, 1);
    ln_packed_kernel<<<3 * 2048, 256>>>(p_h1p, g1, b1);
    conv_fp16_kernel<<<cgrid, 256, CONV_SMEM>>>(
        p_h1p, p_h1p + PSTR_W, p_h1p + 2 * (size_t)PSTR_W, p_w2p, c2b, p_h2, 0);
    ln_head_kernel<<<3 * 2048, 256>>>(p_h2, g2, b2, lw, lb, out + OFF_LOGDUR);

    // join side branch back into the main (capture) stream
    cudaStreamWaitEvent(0, evJoin, 0);

    cudaEventDestroy(evFork);
    cudaEventDestroy(evJoin);
    cudaStreamDestroy(side);
}